// round 1
// baseline (speedup 1.0000x reference)
#include <cuda_runtime.h>
#include <math.h>

#define Bq 2
#define Nq 2048
#define Dq 512
#define Hq 8
#define Fq 2048
#define DHq 64
#define ROWS (Bq*Nq)            // 4096
#define BHq (Bq*Hq)             // 16

// ---------------- scratch (static device globals; no runtime allocation) ----
__device__ float g_Q[ROWS*Dq];
__device__ float g_K[ROWS*Dq];
__device__ float g_V[ROWS*Dq];
__device__ float g_ph[ROWS*Hq];
__device__ float g_S[(size_t)BHq*Nq*Nq];     // 268 MB scores/attn
__device__ float g_msg[ROWS*Dq];
__device__ float g_msgO[ROWS*Dq];
__device__ float g_h1[ROWS*Dq];
__device__ float g_ffn1[ROWS*Fq];
__device__ float g_ffn2[ROWS*Dq];
__device__ float g_rn[ROWS];

// ---------------- generic register-tiled SGEMM: C = A(MxK) @ W(KxN) ---------
// epi bit0: +bias ; bit1: exact GELU
__global__ void sgemm_kernel(const float* __restrict__ A, const float* __restrict__ W,
                             const float* __restrict__ bias, float* __restrict__ C,
                             int M, int K, int Nc, int epi) {
    __shared__ float As[16][65];
    __shared__ float Ws[16][65];
    const int bm = blockIdx.y * 64;
    const int bn = blockIdx.x * 64;
    const int tid = threadIdx.x;
    const int tx = tid & 15, ty = tid >> 4;
    float acc[4][4] = {};
    for (int k0 = 0; k0 < K; k0 += 16) {
        // A tile: As[kk][m] ; consecutive threads read contiguous kk
        #pragma unroll
        for (int i = tid; i < 1024; i += 256) {
            int kk = i & 15, m = i >> 4;
            As[kk][m] = A[(size_t)(bm + m) * K + k0 + kk];
        }
        // W tile: Ws[kk][n] ; coalesced in n
        #pragma unroll
        for (int i = tid; i < 1024; i += 256) {
            int n = i & 63, kk = i >> 6;
            int gn = bn + n;
            Ws[kk][n] = (gn < Nc) ? W[(size_t)(k0 + kk) * Nc + gn] : 0.f;
        }
        __syncthreads();
        #pragma unroll
        for (int kk = 0; kk < 16; kk++) {
            float a[4], w[4];
            #pragma unroll
            for (int i = 0; i < 4; i++) a[i] = As[kk][ty * 4 + i];
            #pragma unroll
            for (int j = 0; j < 4; j++) w[j] = Ws[kk][tx * 4 + j];
            #pragma unroll
            for (int i = 0; i < 4; i++)
                #pragma unroll
                for (int j = 0; j < 4; j++) acc[i][j] += a[i] * w[j];
        }
        __syncthreads();
    }
    #pragma unroll
    for (int i = 0; i < 4; i++) {
        int gm = bm + ty * 4 + i;
        #pragma unroll
        for (int j = 0; j < 4; j++) {
            int gn = bn + tx * 4 + j;
            if (gn >= Nc) continue;
            float v = acc[i][j];
            if (epi & 1) v += bias[gn];
            if (epi & 2) v = 0.5f * v * (1.f + erff(v * 0.7071067811865475f));
            C[(size_t)gm * Nc + gn] = v;
        }
    }
}

// ---------------- 8-wide projection (h@Wp / phase update) -------------------
// mode 0: out = X@W8 + b8 ; mode 1: out = phases + 0.1*pi*tanh(X@W8 + b8)
__global__ void proj8_kernel(const float* __restrict__ X, const float* __restrict__ W8,
                             const float* __restrict__ b8, const float* __restrict__ phases,
                             float* __restrict__ out, int mode) {
    __shared__ float hs[Dq];
    const int row = blockIdx.x;
    const int tid = threadIdx.x;
    hs[tid]       = X[(size_t)row * Dq + tid];
    hs[tid + 256] = X[(size_t)row * Dq + tid + 256];
    __syncthreads();
    const int w = tid >> 5, lane = tid & 31;
    float s = 0.f;
    #pragma unroll
    for (int kk = lane; kk < Dq; kk += 32) s += hs[kk] * W8[kk * Hq + w];
    #pragma unroll
    for (int o = 16; o; o >>= 1) s += __shfl_xor_sync(0xffffffffu, s, o);
    if (lane == 0) {
        s += b8[w];
        if (mode) s = phases[(size_t)row * Hq + w] + 0.31415926535897932f * tanhf(s);
        out[(size_t)row * Hq + w] = s;
    }
}

// ---------------- scores: QK^T/sqrt(dh) * (1+cos(dphi))/2, mask -------------
__global__ void scores_kernel(const float* __restrict__ Q, const float* __restrict__ K,
                              const float* __restrict__ ph, const unsigned char* __restrict__ mask,
                              float* __restrict__ S) {
    const int bh = blockIdx.z;
    const int b = bh >> 3, hh = bh & 7;
    const int n0 = blockIdx.y * 64, m0 = blockIdx.x * 64;
    __shared__ float Qs[64][65];
    __shared__ float Ks[64][65];
    __shared__ float pn[64], pm[64];
    const int tid = threadIdx.x;
    const size_t baseQ = (((size_t)b * Nq + n0) * Hq + hh) * DHq;
    const size_t baseK = (((size_t)b * Nq + m0) * Hq + hh) * DHq;
    #pragma unroll
    for (int i = tid; i < 64 * 64; i += 256) {
        int r = i >> 6, d = i & 63;
        Qs[r][d] = Q[baseQ + (size_t)r * Dq + d];
        Ks[r][d] = K[baseK + (size_t)r * Dq + d];
    }
    if (tid < 64)        pn[tid]      = ph[((size_t)b * Nq + n0 + tid) * Hq + hh];
    else if (tid < 128)  pm[tid - 64] = ph[((size_t)b * Nq + m0 + tid - 64) * Hq + hh];
    __syncthreads();
    const int tx = tid & 15, ty = tid >> 4;
    float acc[4][4] = {};
    #pragma unroll 16
    for (int d = 0; d < 64; d++) {
        float q[4], k[4];
        #pragma unroll
        for (int i = 0; i < 4; i++) q[i] = Qs[ty * 4 + i][d];
        #pragma unroll
        for (int j = 0; j < 4; j++) k[j] = Ks[tx * 4 + j][d];
        #pragma unroll
        for (int i = 0; i < 4; i++)
            #pragma unroll
            for (int j = 0; j < 4; j++) acc[i][j] += q[i] * k[j];
    }
    const float NEG_INF = __int_as_float(0xff800000);
    #pragma unroll
    for (int i = 0; i < 4; i++) {
        int n = n0 + ty * 4 + i;
        #pragma unroll
        for (int j = 0; j < 4; j++) {
            int m = m0 + tx * 4 + j;
            float s = acc[i][j] * 0.125f;                       // 1/sqrt(64)
            s *= 0.5f * (1.f + cosf(pn[ty * 4 + i] - pm[tx * 4 + j]));
            if (mask[b * Nq + m]) s = NEG_INF;
            S[((size_t)bh * Nq + n) * Nq + m] = s;
        }
    }
}

// ---------------- row softmax over N=2048 -----------------------------------
__global__ void softmax_kernel(float* __restrict__ S) {
    __shared__ float red[256];
    const size_t row = blockIdx.x;
    float* p = S + row * (size_t)Nq;
    const int tid = threadIdx.x;
    float v[8];
    float m = -3.4e38f;
    #pragma unroll
    for (int i = 0; i < 8; i++) { v[i] = p[tid + i * 256]; m = fmaxf(m, v[i]); }
    red[tid] = m; __syncthreads();
    #pragma unroll
    for (int o = 128; o; o >>= 1) { if (tid < o) red[tid] = fmaxf(red[tid], red[tid + o]); __syncthreads(); }
    m = red[0]; __syncthreads();
    float s = 0.f;
    #pragma unroll
    for (int i = 0; i < 8; i++) { v[i] = __expf(v[i] - m); s += v[i]; }
    red[tid] = s; __syncthreads();
    #pragma unroll
    for (int o = 128; o; o >>= 1) { if (tid < o) red[tid] += red[tid + o]; __syncthreads(); }
    const float inv = 1.f / red[0];
    #pragma unroll
    for (int i = 0; i < 8; i++) p[tid + i * 256] = v[i] * inv;
}

// ---------------- attn @ V -> messages (B,N,H,DH layout == (B,N,D)) ---------
__global__ void attnv_kernel(const float* __restrict__ S, const float* __restrict__ V,
                             float* __restrict__ Mo) {
    const int bh = blockIdx.y;
    const int b = bh >> 3, hh = bh & 7;
    const int n0 = blockIdx.x * 64;
    __shared__ float As[64][33];
    __shared__ float Vs[32][65];
    const int tid = threadIdx.x;
    const int tx = tid & 15, ty = tid >> 4;
    float acc[4][4] = {};
    for (int k0 = 0; k0 < Nq; k0 += 32) {
        #pragma unroll
        for (int i = tid; i < 64 * 32; i += 256) {
            int nn = i >> 5, kk = i & 31;
            As[nn][kk] = S[((size_t)bh * Nq + n0 + nn) * Nq + k0 + kk];
        }
        #pragma unroll
        for (int i = tid; i < 32 * 64; i += 256) {
            int kk = i >> 6, d = i & 63;
            Vs[kk][d] = V[(((size_t)b * Nq + k0 + kk) * Hq + hh) * DHq + d];
        }
        __syncthreads();
        #pragma unroll
        for (int kk = 0; kk < 32; kk++) {
            float a[4], vv[4];
            #pragma unroll
            for (int i = 0; i < 4; i++) a[i] = As[ty * 4 + i][kk];
            #pragma unroll
            for (int j = 0; j < 4; j++) vv[j] = Vs[kk][tx * 4 + j];
            #pragma unroll
            for (int i = 0; i < 4; i++)
                #pragma unroll
                for (int j = 0; j < 4; j++) acc[i][j] += a[i] * vv[j];
        }
        __syncthreads();
    }
    #pragma unroll
    for (int i = 0; i < 4; i++)
        #pragma unroll
        for (int j = 0; j < 4; j++)
            Mo[(((size_t)b * Nq + n0 + ty * 4 + i) * Hq + hh) * DHq + tx * 4 + j] = acc[i][j];
}

// ---------------- residual add + LayerNorm ----------------------------------
__global__ void addln_kernel(const float* __restrict__ X, const float* __restrict__ Y,
                             const float* __restrict__ g, const float* __restrict__ be,
                             float* __restrict__ out) {
    __shared__ float red[256];
    const size_t row = blockIdx.x;
    const int tid = threadIdx.x;
    float a0 = X[row * Dq + tid]       + Y[row * Dq + tid];
    float a1 = X[row * Dq + tid + 256] + Y[row * Dq + tid + 256];
    red[tid] = a0 + a1; __syncthreads();
    #pragma unroll
    for (int o = 128; o; o >>= 1) { if (tid < o) red[tid] += red[tid + o]; __syncthreads(); }
    const float mu = red[0] * (1.f / Dq); __syncthreads();
    const float d0 = a0 - mu, d1 = a1 - mu;
    red[tid] = d0 * d0 + d1 * d1; __syncthreads();
    #pragma unroll
    for (int o = 128; o; o >>= 1) { if (tid < o) red[tid] += red[tid + o]; __syncthreads(); }
    const float rstd = rsqrtf(red[0] * (1.f / Dq) + 1e-5f);
    out[row * Dq + tid]       = d0 * rstd * g[tid]       + be[tid];
    out[row * Dq + tid + 256] = d1 * rstd * g[tid + 256] + be[tid + 256];
}

// ---------------- delta = mean_row ||h2 - h|| -------------------------------
__global__ void rownorm_kernel(const float* __restrict__ h2, const float* __restrict__ h,
                               float* __restrict__ rn) {
    __shared__ float red[256];
    const size_t row = blockIdx.x;
    const int tid = threadIdx.x;
    float d0 = h2[row * Dq + tid]       - h[row * Dq + tid];
    float d1 = h2[row * Dq + tid + 256] - h[row * Dq + tid + 256];
    red[tid] = d0 * d0 + d1 * d1; __syncthreads();
    #pragma unroll
    for (int o = 128; o; o >>= 1) { if (tid < o) red[tid] += red[tid + o]; __syncthreads(); }
    if (tid == 0) rn[row] = sqrtf(red[0]);
}

__global__ void delta_kernel(const float* __restrict__ rn, float* __restrict__ out) {
    __shared__ float red[256];
    const int tid = threadIdx.x;
    float s = 0.f;
    for (int i = tid; i < ROWS; i += 256) s += rn[i];
    red[tid] = s; __syncthreads();
    #pragma unroll
    for (int o = 128; o; o >>= 1) { if (tid < o) red[tid] += red[tid + o]; __syncthreads(); }
    if (tid == 0) out[0] = red[0] * (1.f / ROWS);
}

// ---------------- launch ----------------------------------------------------
extern "C" void kernel_launch(void* const* d_in, const int* in_sizes, int n_in,
                              void* d_out, int out_size) {
    const float* h      = (const float*)d_in[0];
    const float* phases = (const float*)d_in[1];
    const unsigned char* mask = (const unsigned char*)d_in[2];
    const float* Wq  = (const float*)d_in[3];
    const float* Wk  = (const float*)d_in[4];
    const float* Wp  = (const float*)d_in[5];
    const float* bp  = (const float*)d_in[6];
    const float* Wv  = (const float*)d_in[7];
    const float* Wo  = (const float*)d_in[8];
    const float* W1  = (const float*)d_in[9];
    const float* b1  = (const float*)d_in[10];
    const float* W2  = (const float*)d_in[11];
    const float* b2  = (const float*)d_in[12];
    const float* g1  = (const float*)d_in[13];
    const float* be1 = (const float*)d_in[14];
    const float* g2  = (const float*)d_in[15];
    const float* be2 = (const float*)d_in[16];
    const float* Wph = (const float*)d_in[17];
    const float* bph = (const float*)d_in[18];

    float* out_h2     = (float*)d_out;                       // ROWS*Dq
    float* out_phases = out_h2 + (size_t)ROWS * Dq;          // ROWS*Hq
    float* out_delta  = out_phases + (size_t)ROWS * Hq;      // 1

    float *Q, *K, *V, *ph, *S, *msg, *msgO, *h1, *ffn1, *ffn2, *rn;
    cudaGetSymbolAddress((void**)&Q,    g_Q);
    cudaGetSymbolAddress((void**)&K,    g_K);
    cudaGetSymbolAddress((void**)&V,    g_V);
    cudaGetSymbolAddress((void**)&ph,   g_ph);
    cudaGetSymbolAddress((void**)&S,    g_S);
    cudaGetSymbolAddress((void**)&msg,  g_msg);
    cudaGetSymbolAddress((void**)&msgO, g_msgO);
    cudaGetSymbolAddress((void**)&h1,   g_h1);
    cudaGetSymbolAddress((void**)&ffn1, g_ffn1);
    cudaGetSymbolAddress((void**)&ffn2, g_ffn2);
    cudaGetSymbolAddress((void**)&rn,   g_rn);

    const dim3 gD(Dq / 64, ROWS / 64);        // 8 x 64
    const dim3 gF(Fq / 64, ROWS / 64);        // 32 x 64

    // projections
    sgemm_kernel<<<gD, 256>>>(h, Wq, nullptr, Q, ROWS, Dq, Dq, 0);
    sgemm_kernel<<<gD, 256>>>(h, Wk, nullptr, K, ROWS, Dq, Dq, 0);
    sgemm_kernel<<<gD, 256>>>(h, Wv, nullptr, V, ROWS, Dq, Dq, 0);
    proj8_kernel<<<ROWS, 256>>>(h, Wp, bp, nullptr, ph, 0);

    // attention
    scores_kernel<<<dim3(Nq / 64, Nq / 64, BHq), 256>>>(Q, K, ph, mask, S);
    softmax_kernel<<<BHq * Nq, 256>>>(S);
    attnv_kernel<<<dim3(Nq / 64, BHq), 256>>>(S, V, msg);
    sgemm_kernel<<<gD, 256>>>(msg, Wo, nullptr, msgO, ROWS, Dq, Dq, 0);
    addln_kernel<<<ROWS, 256>>>(h, msgO, g1, be1, h1);

    // FFN
    sgemm_kernel<<<gF, 256>>>(h1, W1, b1, ffn1, ROWS, Dq, Fq, 3);   // bias + gelu
    sgemm_kernel<<<gD, 256>>>(ffn1, W2, b2, ffn2, ROWS, Fq, Dq, 1); // bias
    addln_kernel<<<ROWS, 256>>>(h1, ffn2, g2, be2, out_h2);

    // phase update + delta
    proj8_kernel<<<ROWS, 256>>>(out_h2, Wph, bph, phases, out_phases, 1);
    rownorm_kernel<<<ROWS, 256>>>(out_h2, h, rn);
    delta_kernel<<<1, 256>>>(rn, out_delta);
}

// round 3
// speedup vs baseline: 1.5567x; 1.5567x over previous
#include <cuda_runtime.h>
#include <cuda_bf16.h>
#include <math.h>
#include <stdint.h>

#define Bq 2
#define Nq 2048
#define Dq 512
#define Hq 8
#define Fq 2048
#define DHq 64
#define ROWS (Bq*Nq)            // 4096
#define BHq (Bq*Hq)             // 16

// ---------------- scratch (static device globals) ---------------------------
__device__ float g_Q[ROWS*Dq];
__device__ float g_K[ROWS*Dq];
__device__ float g_V[ROWS*Dq];
__device__ float g_ph[ROWS*Hq];
__device__ float g_S[(size_t)BHq*Nq*Nq];     // 268 MB scores/attn
__device__ float g_msgO[ROWS*Dq];
__device__ float g_h1[ROWS*Dq];
__device__ float g_ffn2[ROWS*Dq];
__device__ float g_rn[ROWS];

__device__ __nv_bfloat16 g_h_hi[ROWS*Dq],   g_h_lo[ROWS*Dq];
__device__ __nv_bfloat16 g_h1_hi[ROWS*Dq],  g_h1_lo[ROWS*Dq];
__device__ __nv_bfloat16 g_msg_hi[ROWS*Dq], g_msg_lo[ROWS*Dq];
__device__ __nv_bfloat16 g_ffn1_hi[(size_t)ROWS*Fq], g_ffn1_lo[(size_t)ROWS*Fq];
__device__ __nv_bfloat16 g_WqT_hi[Dq*Dq], g_WqT_lo[Dq*Dq];
__device__ __nv_bfloat16 g_WkT_hi[Dq*Dq], g_WkT_lo[Dq*Dq];
__device__ __nv_bfloat16 g_WvT_hi[Dq*Dq], g_WvT_lo[Dq*Dq];
__device__ __nv_bfloat16 g_WoT_hi[Dq*Dq], g_WoT_lo[Dq*Dq];
__device__ __nv_bfloat16 g_W1T_hi[(size_t)Fq*Dq], g_W1T_lo[(size_t)Fq*Dq];
__device__ __nv_bfloat16 g_W2T_hi[(size_t)Dq*Fq], g_W2T_lo[(size_t)Dq*Fq];

// ---------------- PTX helpers -----------------------------------------------
__device__ __forceinline__ uint32_t smem_u32(const void* p) {
    return (uint32_t)__cvta_generic_to_shared(p);
}
__device__ __forceinline__ void cp16(uint32_t s, const void* g) {
    asm volatile("cp.async.ca.shared.global [%0], [%1], 16;" :: "r"(s), "l"(g));
}
__device__ __forceinline__ void cp_commit() { asm volatile("cp.async.commit_group;" ::: "memory"); }
__device__ __forceinline__ void cp_wait0()  { asm volatile("cp.async.wait_group 0;" ::: "memory"); }

__device__ __forceinline__ void ldm_x4(uint32_t* r, uint32_t addr) {
    asm volatile("ldmatrix.sync.aligned.m8n8.x4.shared.b16 {%0,%1,%2,%3}, [%4];"
                 : "=r"(r[0]), "=r"(r[1]), "=r"(r[2]), "=r"(r[3]) : "r"(addr));
}
__device__ __forceinline__ void mma16816(float* c, const uint32_t* a, const uint32_t* b) {
    asm volatile("mma.sync.aligned.m16n8k16.row.col.f32.bf16.bf16.f32 "
                 "{%0,%1,%2,%3}, {%4,%5,%6,%7}, {%8,%9}, {%0,%1,%2,%3};"
                 : "+f"(c[0]), "+f"(c[1]), "+f"(c[2]), "+f"(c[3])
                 : "r"(a[0]), "r"(a[1]), "r"(a[2]), "r"(a[3]), "r"(b[0]), "r"(b[1]));
}

// ---------------- HMMA split-bf16 GEMM: C = A(MxK) @ BT(NxK)^T ---------------
// epi bit0: +bias ; bit1: exact GELU ; bit2: write bf16 hi/lo instead of fp32
// A/B row strides = K. M = ROWS. Nc,K multiples of 128/32.
#define TSTR 40                         // smem row stride in bf16 (32 + 8 pad)
__global__ __launch_bounds__(256) void tgemm_kernel(
    const __nv_bfloat16* __restrict__ A_hi, const __nv_bfloat16* __restrict__ A_lo,
    const __nv_bfloat16* __restrict__ B_hi, const __nv_bfloat16* __restrict__ B_lo,
    const float* __restrict__ bias,
    float* __restrict__ Cf, __nv_bfloat16* __restrict__ C_hi, __nv_bfloat16* __restrict__ C_lo,
    int K, int Nc, int epi)
{
    __shared__ __align__(128) __nv_bfloat16 sm[2][2][128 * TSTR];   // [stage][A/B]
    const int tid = threadIdx.x;
    const int warp = tid >> 5, lane = tid & 31;
    const int wm = warp >> 1, wn = warp & 1;    // 4 x 2 warp grid
    const int bm = blockIdx.y * 128, bn = blockIdx.x * 128;

    const int KC = K >> 5;
    const int NCH = 3 * KC;
    const __nv_bfloat16* PA[3] = {A_hi, A_hi, A_lo};
    const __nv_bfloat16* PB[3] = {B_hi, B_lo, B_hi};

    const int lrow = tid >> 2, lch = (tid & 3) << 3;     // loader: row 0..63(+64), 16B chunk
    uint32_t sAu[2], sBu[2];
    sAu[0] = smem_u32(sm[0][0]); sBu[0] = smem_u32(sm[0][1]);
    sAu[1] = smem_u32(sm[1][0]); sBu[1] = smem_u32(sm[1][1]);

    float acc[2][8][4];
    #pragma unroll
    for (int i = 0; i < 2; i++)
        #pragma unroll
        for (int j = 0; j < 8; j++)
            #pragma unroll
            for (int q = 0; q < 4; q++) acc[i][j][q] = 0.f;

    auto issue = [&](int c, int s) {
        const int pass = c / KC;
        const int kc = (c - pass * KC) << 5;
        const __nv_bfloat16* pa = PA[pass];
        const __nv_bfloat16* pb = PB[pass];
        #pragma unroll
        for (int i = 0; i < 2; i++) {
            const int row = lrow + i * 64;
            const uint32_t so = (uint32_t)(row * TSTR + lch) * 2;
            cp16(sAu[s] + so, pa + (size_t)(bm + row) * K + kc + lch);
            cp16(sBu[s] + so, pb + (size_t)(bn + row) * K + kc + lch);
        }
        cp_commit();
    };

    issue(0, 0);
    for (int c = 0; c < NCH; c++) {
        const int s = c & 1;
        cp_wait0();
        __syncthreads();
        if (c + 1 < NCH) issue(c + 1, s ^ 1);
        // compute from stage s
        #pragma unroll
        for (int ks = 0; ks < 2; ks++) {
            uint32_t a[2][4];
            #pragma unroll
            for (int mt = 0; mt < 2; mt++) {
                const int row = wm * 32 + mt * 16 + (lane & 15);
                const int col = ks * 16 + ((lane >> 4) << 3);
                ldm_x4(a[mt], sAu[s] + (uint32_t)(row * TSTR + col) * 2);
            }
            uint32_t b[4][4];
            #pragma unroll
            for (int nt4 = 0; nt4 < 4; nt4++) {
                const int nrow = wn * 64 + nt4 * 16 + ((lane >> 4) << 3) + (lane & 7);
                const int kcol = ks * 16 + (((lane >> 3) & 1) << 3);
                ldm_x4(b[nt4], sBu[s] + (uint32_t)(nrow * TSTR + kcol) * 2);
            }
            #pragma unroll
            for (int mt = 0; mt < 2; mt++)
                #pragma unroll
                for (int nt = 0; nt < 8; nt++)
                    mma16816(acc[mt][nt], a[mt], &b[nt >> 1][(nt & 1) * 2]);
        }
        __syncthreads();
    }

    // epilogue
    #pragma unroll
    for (int mt = 0; mt < 2; mt++) {
        const int r0 = bm + wm * 32 + mt * 16 + (lane >> 2);
        #pragma unroll
        for (int nt = 0; nt < 8; nt++) {
            const int gn = bn + wn * 64 + nt * 8 + ((lane & 3) << 1);
            #pragma unroll
            for (int half = 0; half < 2; half++) {
                const int row = r0 + half * 8;
                float v0 = acc[mt][nt][half * 2 + 0];
                float v1 = acc[mt][nt][half * 2 + 1];
                if (epi & 1) { v0 += bias[gn]; v1 += bias[gn + 1]; }
                if (epi & 2) {
                    v0 = 0.5f * v0 * (1.f + erff(v0 * 0.7071067811865475f));
                    v1 = 0.5f * v1 * (1.f + erff(v1 * 0.7071067811865475f));
                }
                if (epi & 4) {
                    const __nv_bfloat16 h0 = __float2bfloat16(v0);
                    const __nv_bfloat16 h1 = __float2bfloat16(v1);
                    const size_t idx = (size_t)row * Nc + gn;
                    C_hi[idx] = h0;      C_hi[idx + 1] = h1;
                    C_lo[idx] = __float2bfloat16(v0 - __bfloat162float(h0));
                    C_lo[idx + 1] = __float2bfloat16(v1 - __bfloat162float(h1));
                } else {
                    *(float2*)(Cf + (size_t)row * Nc + gn) = make_float2(v0, v1);
                }
            }
        }
    }
}

// ---------------- weight transpose + bf16 split: W(KxN) -> BT(NxK) ----------
__global__ void wtrans_kernel(const float* __restrict__ W, __nv_bfloat16* __restrict__ T_hi,
                              __nv_bfloat16* __restrict__ T_lo, int K, int Nc) {
    __shared__ float t[32][33];
    const int k0 = blockIdx.y * 32, n0 = blockIdx.x * 32;
    const int tx = threadIdx.x, ty = threadIdx.y;
    #pragma unroll
    for (int i = ty; i < 32; i += 8) t[i][tx] = W[(size_t)(k0 + i) * Nc + n0 + tx];
    __syncthreads();
    #pragma unroll
    for (int i = ty; i < 32; i += 8) {
        const float v = t[tx][i];                  // = W[k0+tx][n0+i]
        const __nv_bfloat16 hi = __float2bfloat16(v);
        T_hi[(size_t)(n0 + i) * K + k0 + tx] = hi;
        T_lo[(size_t)(n0 + i) * K + k0 + tx] = __float2bfloat16(v - __bfloat162float(hi));
    }
}

// ---------------- elementwise bf16 split ------------------------------------
__global__ void fsplit_kernel(const float* __restrict__ X, __nv_bfloat16* __restrict__ hi,
                              __nv_bfloat16* __restrict__ lo, int n) {
    const int i = blockIdx.x * 256 + threadIdx.x;
    if (i < n) {
        const float v = X[i];
        const __nv_bfloat16 h = __float2bfloat16(v);
        hi[i] = h;
        lo[i] = __float2bfloat16(v - __bfloat162float(h));
    }
}

// ---------------- 8-wide projection (h@Wp / phase update) -------------------
__global__ void proj8_kernel(const float* __restrict__ X, const float* __restrict__ W8,
                             const float* __restrict__ b8, const float* __restrict__ phases,
                             float* __restrict__ out, int mode) {
    __shared__ float hs[Dq];
    const int row = blockIdx.x;
    const int tid = threadIdx.x;
    hs[tid]       = X[(size_t)row * Dq + tid];
    hs[tid + 256] = X[(size_t)row * Dq + tid + 256];
    __syncthreads();
    const int w = tid >> 5, lane = tid & 31;
    float s = 0.f;
    #pragma unroll
    for (int kk = lane; kk < Dq; kk += 32) s += hs[kk] * W8[kk * Hq + w];
    #pragma unroll
    for (int o = 16; o; o >>= 1) s += __shfl_xor_sync(0xffffffffu, s, o);
    if (lane == 0) {
        s += b8[w];
        if (mode) s = phases[(size_t)row * Hq + w] + 0.31415926535897932f * tanhf(s);
        out[(size_t)row * Hq + w] = s;
    }
}

// ---------------- scores: QK^T/sqrt(dh) * (1+cos(dphi))/2, mask -------------
__global__ void scores_kernel(const float* __restrict__ Q, const float* __restrict__ K,
                              const float* __restrict__ ph, const unsigned char* __restrict__ mask,
                              float* __restrict__ S) {
    const int bh = blockIdx.z;
    const int b = bh >> 3, hh = bh & 7;
    const int n0 = blockIdx.y * 64, m0 = blockIdx.x * 64;
    __shared__ float Qs[64][65];
    __shared__ float Ks[64][65];
    __shared__ float pn[64], pm[64];
    const int tid = threadIdx.x;
    const size_t baseQ = (((size_t)b * Nq + n0) * Hq + hh) * DHq;
    const size_t baseK = (((size_t)b * Nq + m0) * Hq + hh) * DHq;
    #pragma unroll
    for (int i = tid; i < 64 * 64; i += 256) {
        int r = i >> 6, d = i & 63;
        Qs[r][d] = Q[baseQ + (size_t)r * Dq + d];
        Ks[r][d] = K[baseK + (size_t)r * Dq + d];
    }
    if (tid < 64)        pn[tid]      = ph[((size_t)b * Nq + n0 + tid) * Hq + hh];
    else if (tid < 128)  pm[tid - 64] = ph[((size_t)b * Nq + m0 + tid - 64) * Hq + hh];
    __syncthreads();
    const int tx = tid & 15, ty = tid >> 4;
    float acc[4][4] = {};
    #pragma unroll 16
    for (int d = 0; d < 64; d++) {
        float q[4], k[4];
        #pragma unroll
        for (int i = 0; i < 4; i++) q[i] = Qs[ty * 4 + i][d];
        #pragma unroll
        for (int j = 0; j < 4; j++) k[j] = Ks[tx * 4 + j][d];
        #pragma unroll
        for (int i = 0; i < 4; i++)
            #pragma unroll
            for (int j = 0; j < 4; j++) acc[i][j] += q[i] * k[j];
    }
    const float NEG_INF = __int_as_float(0xff800000);
    #pragma unroll
    for (int i = 0; i < 4; i++) {
        int n = n0 + ty * 4 + i;
        #pragma unroll
        for (int j = 0; j < 4; j++) {
            int m = m0 + tx * 4 + j;
            float s = acc[i][j] * 0.125f;
            s *= 0.5f * (1.f + cosf(pn[ty * 4 + i] - pm[tx * 4 + j]));
            if (mask[b * Nq + m]) s = NEG_INF;
            S[((size_t)bh * Nq + n) * Nq + m] = s;
        }
    }
}

// ---------------- row softmax over N=2048 -----------------------------------
__global__ void softmax_kernel(float* __restrict__ S) {
    __shared__ float red[256];
    const size_t row = blockIdx.x;
    float* p = S + row * (size_t)Nq;
    const int tid = threadIdx.x;
    float v[8];
    float m = -3.4e38f;
    #pragma unroll
    for (int i = 0; i < 8; i++) { v[i] = p[tid + i * 256]; m = fmaxf(m, v[i]); }
    red[tid] = m; __syncthreads();
    #pragma unroll
    for (int o = 128; o; o >>= 1) { if (tid < o) red[tid] = fmaxf(red[tid], red[tid + o]); __syncthreads(); }
    m = red[0]; __syncthreads();
    float s = 0.f;
    #pragma unroll
    for (int i = 0; i < 8; i++) { v[i] = __expf(v[i] - m); s += v[i]; }
    red[tid] = s; __syncthreads();
    #pragma unroll
    for (int o = 128; o; o >>= 1) { if (tid < o) red[tid] += red[tid + o]; __syncthreads(); }
    const float inv = 1.f / red[0];
    #pragma unroll
    for (int i = 0; i < 8; i++) p[tid + i * 256] = v[i] * inv;
}

// ---------------- attn @ V -> messages (split-bf16 out) ---------------------
__global__ void attnv_kernel(const float* __restrict__ S, const float* __restrict__ V,
                             __nv_bfloat16* __restrict__ Mhi, __nv_bfloat16* __restrict__ Mlo) {
    const int bh = blockIdx.y;
    const int b = bh >> 3, hh = bh & 7;
    const int n0 = blockIdx.x * 64;
    __shared__ float As[64][33];
    __shared__ float Vs[32][65];
    const int tid = threadIdx.x;
    const int tx = tid & 15, ty = tid >> 4;
    float acc[4][4] = {};
    for (int k0 = 0; k0 < Nq; k0 += 32) {
        #pragma unroll
        for (int i = tid; i < 64 * 32; i += 256) {
            int nn = i >> 5, kk = i & 31;
            As[nn][kk] = S[((size_t)bh * Nq + n0 + nn) * Nq + k0 + kk];
        }
        #pragma unroll
        for (int i = tid; i < 32 * 64; i += 256) {
            int kk = i >> 6, d = i & 63;
            Vs[kk][d] = V[(((size_t)b * Nq + k0 + kk) * Hq + hh) * DHq + d];
        }
        __syncthreads();
        #pragma unroll
        for (int kk = 0; kk < 32; kk++) {
            float a[4], vv[4];
            #pragma unroll
            for (int i = 0; i < 4; i++) a[i] = As[ty * 4 + i][kk];
            #pragma unroll
            for (int j = 0; j < 4; j++) vv[j] = Vs[kk][tx * 4 + j];
            #pragma unroll
            for (int i = 0; i < 4; i++)
                #pragma unroll
                for (int j = 0; j < 4; j++) acc[i][j] += a[i] * vv[j];
        }
        __syncthreads();
    }
    #pragma unroll
    for (int i = 0; i < 4; i++)
        #pragma unroll
        for (int j = 0; j < 4; j++) {
            const size_t idx = (((size_t)b * Nq + n0 + ty * 4 + i) * Hq + hh) * DHq + tx * 4 + j;
            const float v = acc[i][j];
            const __nv_bfloat16 hi = __float2bfloat16(v);
            Mhi[idx] = hi;
            Mlo[idx] = __float2bfloat16(v - __bfloat162float(hi));
        }
}

// ---------------- residual add + LayerNorm (+ optional split out) -----------
__global__ void addln_kernel(const float* __restrict__ X, const float* __restrict__ Y,
                             const float* __restrict__ g, const float* __restrict__ be,
                             float* __restrict__ out,
                             __nv_bfloat16* __restrict__ ohi, __nv_bfloat16* __restrict__ olo) {
    __shared__ float red[256];
    const size_t row = blockIdx.x;
    const int tid = threadIdx.x;
    float a0 = X[row * Dq + tid]       + Y[row * Dq + tid];
    float a1 = X[row * Dq + tid + 256] + Y[row * Dq + tid + 256];
    red[tid] = a0 + a1; __syncthreads();
    #pragma unroll
    for (int o = 128; o; o >>= 1) { if (tid < o) red[tid] += red[tid + o]; __syncthreads(); }
    const float mu = red[0] * (1.f / Dq); __syncthreads();
    const float d0 = a0 - mu, d1 = a1 - mu;
    red[tid] = d0 * d0 + d1 * d1; __syncthreads();
    #pragma unroll
    for (int o = 128; o; o >>= 1) { if (tid < o) red[tid] += red[tid + o]; __syncthreads(); }
    const float rstd = rsqrtf(red[0] * (1.f / Dq) + 1e-5f);
    const float r0 = d0 * rstd * g[tid]       + be[tid];
    const float r1 = d1 * rstd * g[tid + 256] + be[tid + 256];
    out[row * Dq + tid]       = r0;
    out[row * Dq + tid + 256] = r1;
    if (ohi) {
        const __nv_bfloat16 h0 = __float2bfloat16(r0);
        const __nv_bfloat16 h1b = __float2bfloat16(r1);
        ohi[row * Dq + tid]       = h0;
        ohi[row * Dq + tid + 256] = h1b;
        olo[row * Dq + tid]       = __float2bfloat16(r0 - __bfloat162float(h0));
        olo[row * Dq + tid + 256] = __float2bfloat16(r1 - __bfloat162float(h1b));
    }
}

// ---------------- delta = mean_row ||h2 - h|| -------------------------------
__global__ void rownorm_kernel(const float* __restrict__ h2, const float* __restrict__ h,
                               float* __restrict__ rn) {
    __shared__ float red[256];
    const size_t row = blockIdx.x;
    const int tid = threadIdx.x;
    float d0 = h2[row * Dq + tid]       - h[row * Dq + tid];
    float d1 = h2[row * Dq + tid + 256] - h[row * Dq + tid + 256];
    red[tid] = d0 * d0 + d1 * d1; __syncthreads();
    #pragma unroll
    for (int o = 128; o; o >>= 1) { if (tid < o) red[tid] += red[tid + o]; __syncthreads(); }
    if (tid == 0) rn[row] = sqrtf(red[0]);
}

__global__ void delta_kernel(const float* __restrict__ rn, float* __restrict__ out) {
    __shared__ float red[256];
    const int tid = threadIdx.x;
    float s = 0.f;
    for (int i = tid; i < ROWS; i += 256) s += rn[i];
    red[tid] = s; __syncthreads();
    #pragma unroll
    for (int o = 128; o; o >>= 1) { if (tid < o) red[tid] += red[tid + o]; __syncthreads(); }
    if (tid == 0) out[0] = red[0] * (1.f / ROWS);
}

// ---------------- launch ----------------------------------------------------
extern "C" void kernel_launch(void* const* d_in, const int* in_sizes, int n_in,
                              void* d_out, int out_size) {
    const float* h      = (const float*)d_in[0];
    const float* phases = (const float*)d_in[1];
    const unsigned char* mask = (const unsigned char*)d_in[2];
    const float* Wq  = (const float*)d_in[3];
    const float* Wk  = (const float*)d_in[4];
    const float* Wp  = (const float*)d_in[5];
    const float* bp  = (const float*)d_in[6];
    const float* Wv  = (const float*)d_in[7];
    const float* Wo  = (const float*)d_in[8];
    const float* W1  = (const float*)d_in[9];
    const float* b1  = (const float*)d_in[10];
    const float* W2  = (const float*)d_in[11];
    const float* b2  = (const float*)d_in[12];
    const float* g1  = (const float*)d_in[13];
    const float* be1 = (const float*)d_in[14];
    const float* g2  = (const float*)d_in[15];
    const float* be2 = (const float*)d_in[16];
    const float* Wph = (const float*)d_in[17];
    const float* bph = (const float*)d_in[18];

    float* out_h2     = (float*)d_out;
    float* out_phases = out_h2 + (size_t)ROWS * Dq;
    float* out_delta  = out_phases + (size_t)ROWS * Hq;

    float *Q, *K, *V, *ph, *S, *msgO, *h1, *ffn2, *rn;
    __nv_bfloat16 *hhi, *hlo, *h1hi, *h1lo, *mhi, *mlo, *f1hi, *f1lo;
    __nv_bfloat16 *WqTh, *WqTl, *WkTh, *WkTl, *WvTh, *WvTl, *WoTh, *WoTl, *W1Th, *W1Tl, *W2Th, *W2Tl;
    cudaGetSymbolAddress((void**)&Q, g_Q);       cudaGetSymbolAddress((void**)&K, g_K);
    cudaGetSymbolAddress((void**)&V, g_V);       cudaGetSymbolAddress((void**)&ph, g_ph);
    cudaGetSymbolAddress((void**)&S, g_S);       cudaGetSymbolAddress((void**)&msgO, g_msgO);
    cudaGetSymbolAddress((void**)&h1, g_h1);     cudaGetSymbolAddress((void**)&ffn2, g_ffn2);
    cudaGetSymbolAddress((void**)&rn, g_rn);
    cudaGetSymbolAddress((void**)&hhi, g_h_hi);  cudaGetSymbolAddress((void**)&hlo, g_h_lo);
    cudaGetSymbolAddress((void**)&h1hi, g_h1_hi);cudaGetSymbolAddress((void**)&h1lo, g_h1_lo);
    cudaGetSymbolAddress((void**)&mhi, g_msg_hi);cudaGetSymbolAddress((void**)&mlo, g_msg_lo);
    cudaGetSymbolAddress((void**)&f1hi, g_ffn1_hi); cudaGetSymbolAddress((void**)&f1lo, g_ffn1_lo);
    cudaGetSymbolAddress((void**)&WqTh, g_WqT_hi); cudaGetSymbolAddress((void**)&WqTl, g_WqT_lo);
    cudaGetSymbolAddress((void**)&WkTh, g_WkT_hi); cudaGetSymbolAddress((void**)&WkTl, g_WkT_lo);
    cudaGetSymbolAddress((void**)&WvTh, g_WvT_hi); cudaGetSymbolAddress((void**)&WvTl, g_WvT_lo);
    cudaGetSymbolAddress((void**)&WoTh, g_WoT_hi); cudaGetSymbolAddress((void**)&WoTl, g_WoT_lo);
    cudaGetSymbolAddress((void**)&W1Th, g_W1T_hi); cudaGetSymbolAddress((void**)&W1Tl, g_W1T_lo);
    cudaGetSymbolAddress((void**)&W2Th, g_W2T_hi); cudaGetSymbolAddress((void**)&W2Tl, g_W2T_lo);

    const dim3 tb(32, 8);
    wtrans_kernel<<<dim3(Dq / 32, Dq / 32), tb>>>(Wq, WqTh, WqTl, Dq, Dq);
    wtrans_kernel<<<dim3(Dq / 32, Dq / 32), tb>>>(Wk, WkTh, WkTl, Dq, Dq);
    wtrans_kernel<<<dim3(Dq / 32, Dq / 32), tb>>>(Wv, WvTh, WvTl, Dq, Dq);
    wtrans_kernel<<<dim3(Dq / 32, Dq / 32), tb>>>(Wo, WoTh, WoTl, Dq, Dq);
    wtrans_kernel<<<dim3(Fq / 32, Dq / 32), tb>>>(W1, W1Th, W1Tl, Dq, Fq);
    wtrans_kernel<<<dim3(Dq / 32, Fq / 32), tb>>>(W2, W2Th, W2Tl, Fq, Dq);
    fsplit_kernel<<<(ROWS * Dq + 255) / 256, 256>>>(h, hhi, hlo, ROWS * Dq);

    const dim3 gDD(Dq / 128, ROWS / 128);   // 4 x 32
    const dim3 gDF(Fq / 128, ROWS / 128);   // 16 x 32

    // projections (tensor cores via mma.sync)
    tgemm_kernel<<<gDD, 256>>>(hhi, hlo, WqTh, WqTl, nullptr, Q, nullptr, nullptr, Dq, Dq, 0);
    tgemm_kernel<<<gDD, 256>>>(hhi, hlo, WkTh, WkTl, nullptr, K, nullptr, nullptr, Dq, Dq, 0);
    tgemm_kernel<<<gDD, 256>>>(hhi, hlo, WvTh, WvTl, nullptr, V, nullptr, nullptr, Dq, Dq, 0);
    proj8_kernel<<<ROWS, 256>>>(h, Wp, bp, nullptr, ph, 0);

    // attention (fp32)
    scores_kernel<<<dim3(Nq / 64, Nq / 64, BHq), 256>>>(Q, K, ph, mask, S);
    softmax_kernel<<<BHq * Nq, 256>>>(S);
    attnv_kernel<<<dim3(Nq / 64, BHq), 256>>>(S, V, mhi, mlo);
    tgemm_kernel<<<gDD, 256>>>(mhi, mlo, WoTh, WoTl, nullptr, msgO, nullptr, nullptr, Dq, Dq, 0);
    addln_kernel<<<ROWS, 256>>>(h, msgO, g1, be1, h1, h1hi, h1lo);

    // FFN (tensor cores)
    tgemm_kernel<<<gDF, 256>>>(h1hi, h1lo, W1Th, W1Tl, b1, nullptr, f1hi, f1lo, Dq, Fq, 7);
    tgemm_kernel<<<gDD, 256>>>(f1hi, f1lo, W2Th, W2Tl, b2, ffn2, nullptr, nullptr, Fq, Dq, 1);
    addln_kernel<<<ROWS, 256>>>(h1, ffn2, g2, be2, out_h2, nullptr, nullptr);

    // phase update + delta
    proj8_kernel<<<ROWS, 256>>>(out_h2, Wph, bph, phases, out_phases, 1);
    rownorm_kernel<<<ROWS, 256>>>(out_h2, h, rn);
    delta_kernel<<<1, 256>>>(rn, out_delta);
}

// round 4
// speedup vs baseline: 4.6647x; 2.9964x over previous
#include <cuda_runtime.h>
#include <cuda_bf16.h>
#include <math.h>
#include <stdint.h>

#define Bq 2
#define Nq 2048
#define Dq 512
#define Hq 8
#define Fq 2048
#define DHq 64
#define ROWS (Bq*Nq)            // 4096
#define BHq (Bq*Hq)             // 16

// ---------------- scratch (static device globals) ---------------------------
__device__ float g_ph[ROWS*Hq];
__device__ float g_cph[BHq*Nq];
__device__ float g_sph[BHq*Nq];
__device__ float g_msgO[ROWS*Dq];
__device__ float g_h1[ROWS*Dq];
__device__ float g_ffn2[ROWS*Dq];
__device__ float g_rn[ROWS];

__device__ __nv_bfloat16 g_Qb[ROWS*Dq], g_Kb[ROWS*Dq], g_Vb[ROWS*Dq];
__device__ __nv_bfloat16 g_h_hi[ROWS*Dq],   g_h_lo[ROWS*Dq];
__device__ __nv_bfloat16 g_h1_hi[ROWS*Dq],  g_h1_lo[ROWS*Dq];
__device__ __nv_bfloat16 g_msg_hi[ROWS*Dq];
__device__ __nv_bfloat16 g_ffn1_hi[(size_t)ROWS*Fq], g_ffn1_lo[(size_t)ROWS*Fq];
__device__ __nv_bfloat16 g_WqT_hi[Dq*Dq], g_WqT_lo[Dq*Dq];
__device__ __nv_bfloat16 g_WkT_hi[Dq*Dq], g_WkT_lo[Dq*Dq];
__device__ __nv_bfloat16 g_WvT_hi[Dq*Dq], g_WvT_lo[Dq*Dq];
__device__ __nv_bfloat16 g_WoT_hi[Dq*Dq], g_WoT_lo[Dq*Dq];
__device__ __nv_bfloat16 g_W1T_hi[(size_t)Fq*Dq], g_W1T_lo[(size_t)Fq*Dq];
__device__ __nv_bfloat16 g_W2T_hi[(size_t)Dq*Fq], g_W2T_lo[(size_t)Dq*Fq];

// ---------------- PTX helpers -----------------------------------------------
__device__ __forceinline__ uint32_t smem_u32(const void* p) {
    return (uint32_t)__cvta_generic_to_shared(p);
}
__device__ __forceinline__ void cp16(uint32_t s, const void* g) {
    asm volatile("cp.async.ca.shared.global [%0], [%1], 16;" :: "r"(s), "l"(g));
}
__device__ __forceinline__ void cp_commit() { asm volatile("cp.async.commit_group;" ::: "memory"); }
__device__ __forceinline__ void cp_wait0()  { asm volatile("cp.async.wait_group 0;" ::: "memory"); }
__device__ __forceinline__ void cp_wait1()  { asm volatile("cp.async.wait_group 1;" ::: "memory"); }

__device__ __forceinline__ void ldm_x4(uint32_t* r, uint32_t addr) {
    asm volatile("ldmatrix.sync.aligned.m8n8.x4.shared.b16 {%0,%1,%2,%3}, [%4];"
                 : "=r"(r[0]), "=r"(r[1]), "=r"(r[2]), "=r"(r[3]) : "r"(addr));
}
__device__ __forceinline__ void ldm_x4_t(uint32_t* r, uint32_t addr) {
    asm volatile("ldmatrix.sync.aligned.m8n8.x4.trans.shared.b16 {%0,%1,%2,%3}, [%4];"
                 : "=r"(r[0]), "=r"(r[1]), "=r"(r[2]), "=r"(r[3]) : "r"(addr));
}
__device__ __forceinline__ void mma16816(float* c, const uint32_t* a, const uint32_t* b) {
    asm volatile("mma.sync.aligned.m16n8k16.row.col.f32.bf16.bf16.f32 "
                 "{%0,%1,%2,%3}, {%4,%5,%6,%7}, {%8,%9}, {%0,%1,%2,%3};"
                 : "+f"(c[0]), "+f"(c[1]), "+f"(c[2]), "+f"(c[3])
                 : "r"(a[0]), "r"(a[1]), "r"(a[2]), "r"(a[3]), "r"(b[0]), "r"(b[1]));
}
__device__ __forceinline__ uint32_t pack2(float x, float y) {
    __nv_bfloat162 t = __float22bfloat162_rn(make_float2(x, y));
    return *(uint32_t*)&t;
}

// ---------------- HMMA bf16 GEMM: C = A(MxK) @ BT(NxK)^T ---------------------
// terms: 1 (hi*hi) or 3 (split Markidis)
// epi bit0: +bias ; bit1: GELU ; bit2: bf16 hi/lo out ; bit3: plain bf16 out
#define TSTR 40
__global__ __launch_bounds__(256) void tgemm_kernel(
    const __nv_bfloat16* __restrict__ A_hi, const __nv_bfloat16* __restrict__ A_lo,
    const __nv_bfloat16* __restrict__ B_hi, const __nv_bfloat16* __restrict__ B_lo,
    const float* __restrict__ bias,
    float* __restrict__ Cf, __nv_bfloat16* __restrict__ C_hi, __nv_bfloat16* __restrict__ C_lo,
    int K, int Nc, int epi, int terms)
{
    __shared__ __align__(128) __nv_bfloat16 sm[2][2][128 * TSTR];
    const int tid = threadIdx.x;
    const int warp = tid >> 5, lane = tid & 31;
    const int wm = warp >> 1, wn = warp & 1;
    const int bm = blockIdx.y * 128, bn = blockIdx.x * 128;

    const int KC = K >> 5;
    const int NCH = terms * KC;
    const __nv_bfloat16* PA[3] = {A_hi, A_hi, A_lo};
    const __nv_bfloat16* PB[3] = {B_hi, B_lo, B_hi};

    const int lrow = tid >> 2, lch = (tid & 3) << 3;
    uint32_t sAu[2], sBu[2];
    sAu[0] = smem_u32(sm[0][0]); sBu[0] = smem_u32(sm[0][1]);
    sAu[1] = smem_u32(sm[1][0]); sBu[1] = smem_u32(sm[1][1]);

    float acc[2][8][4];
    #pragma unroll
    for (int i = 0; i < 2; i++)
        #pragma unroll
        for (int j = 0; j < 8; j++)
            #pragma unroll
            for (int q = 0; q < 4; q++) acc[i][j][q] = 0.f;

    auto issue = [&](int c, int s) {
        const int pass = c / KC;
        const int kc = (c - pass * KC) << 5;
        const __nv_bfloat16* pa = PA[pass];
        const __nv_bfloat16* pb = PB[pass];
        #pragma unroll
        for (int i = 0; i < 2; i++) {
            const int row = lrow + i * 64;
            const uint32_t so = (uint32_t)(row * TSTR + lch) * 2;
            cp16(sAu[s] + so, pa + (size_t)(bm + row) * K + kc + lch);
            cp16(sBu[s] + so, pb + (size_t)(bn + row) * K + kc + lch);
        }
        cp_commit();
    };

    issue(0, 0);
    for (int c = 0; c < NCH; c++) {
        const int s = c & 1;
        cp_wait0();
        __syncthreads();
        if (c + 1 < NCH) issue(c + 1, s ^ 1);
        #pragma unroll
        for (int ks = 0; ks < 2; ks++) {
            uint32_t a[2][4];
            #pragma unroll
            for (int mt = 0; mt < 2; mt++) {
                const int row = wm * 32 + mt * 16 + (lane & 15);
                const int col = ks * 16 + ((lane >> 4) << 3);
                ldm_x4(a[mt], sAu[s] + (uint32_t)(row * TSTR + col) * 2);
            }
            uint32_t b[4][4];
            #pragma unroll
            for (int nt4 = 0; nt4 < 4; nt4++) {
                const int nrow = wn * 64 + nt4 * 16 + ((lane >> 4) << 3) + (lane & 7);
                const int kcol = ks * 16 + (((lane >> 3) & 1) << 3);
                ldm_x4(b[nt4], sBu[s] + (uint32_t)(nrow * TSTR + kcol) * 2);
            }
            #pragma unroll
            for (int mt = 0; mt < 2; mt++)
                #pragma unroll
                for (int nt = 0; nt < 8; nt++)
                    mma16816(acc[mt][nt], a[mt], &b[nt >> 1][(nt & 1) * 2]);
        }
        __syncthreads();
    }

    #pragma unroll
    for (int mt = 0; mt < 2; mt++) {
        const int r0 = bm + wm * 32 + mt * 16 + (lane >> 2);
        #pragma unroll
        for (int nt = 0; nt < 8; nt++) {
            const int gn = bn + wn * 64 + nt * 8 + ((lane & 3) << 1);
            #pragma unroll
            for (int half = 0; half < 2; half++) {
                const int row = r0 + half * 8;
                float v0 = acc[mt][nt][half * 2 + 0];
                float v1 = acc[mt][nt][half * 2 + 1];
                if (epi & 1) { v0 += bias[gn]; v1 += bias[gn + 1]; }
                if (epi & 2) {
                    v0 = 0.5f * v0 * (1.f + erff(v0 * 0.7071067811865475f));
                    v1 = 0.5f * v1 * (1.f + erff(v1 * 0.7071067811865475f));
                }
                const size_t idx = (size_t)row * Nc + gn;
                if (epi & 4) {
                    const __nv_bfloat16 h0 = __float2bfloat16(v0);
                    const __nv_bfloat16 h1 = __float2bfloat16(v1);
                    C_hi[idx] = h0;      C_hi[idx + 1] = h1;
                    C_lo[idx] = __float2bfloat16(v0 - __bfloat162float(h0));
                    C_lo[idx + 1] = __float2bfloat16(v1 - __bfloat162float(h1));
                } else if (epi & 8) {
                    *(__nv_bfloat162*)(C_hi + idx) =
                        __float22bfloat162_rn(make_float2(v0, v1));
                } else {
                    *(float2*)(Cf + idx) = make_float2(v0, v1);
                }
            }
        }
    }
}

// ---------------- fused flash attention (bf16 HMMA) --------------------------
// grid (Nq/128, BHq), block 256 (8 warps x 16 rows)
#define FSTR 72
#define FLASH_STAGE 38016
#define FLASH_SMEM (18432 + 2 * FLASH_STAGE)
__global__ __launch_bounds__(256) void flash_kernel(
    const __nv_bfloat16* __restrict__ Qb, const __nv_bfloat16* __restrict__ Kb,
    const __nv_bfloat16* __restrict__ Vb,
    const float* __restrict__ cph, const float* __restrict__ sph,
    const unsigned char* __restrict__ mask,
    __nv_bfloat16* __restrict__ Mhi)
{
    extern __shared__ __align__(128) unsigned char fsm[];
    const int tid = threadIdx.x, warp = tid >> 5, lane = tid & 31;
    const int bh = blockIdx.y, b = bh >> 3, hh = bh & 7;
    const int n0 = blockIdx.x * 128;
    const uint32_t sb = smem_u32(fsm);

    // Q tile (group 0)
    const __nv_bfloat16* gQ = Qb + ((size_t)b * Nq + n0) * Dq + hh * DHq;
    #pragma unroll
    for (int i = 0; i < 4; i++) {
        const int id = tid + i * 256, row = id >> 3, ch = id & 7;
        cp16(sb + row * 144 + ch * 16, gQ + (size_t)row * Dq + ch * 8);
    }
    cp_commit();

    auto issueKV = [&](int step, int s) {
        const uint32_t ku = sb + 18432 + s * FLASH_STAGE;
        const uint32_t vu = ku + 18432, cku = ku + 36864, sku = ku + 37376, mku = ku + 37888;
        const __nv_bfloat16* gK = Kb + ((size_t)b * Nq + step * 128) * Dq + hh * DHq;
        const __nv_bfloat16* gV = Vb + ((size_t)b * Nq + step * 128) * Dq + hh * DHq;
        #pragma unroll
        for (int i = 0; i < 4; i++) {
            const int id = tid + i * 256, row = id >> 3, ch = id & 7;
            cp16(ku + row * 144 + ch * 16, gK + (size_t)row * Dq + ch * 8);
            cp16(vu + row * 144 + ch * 16, gV + (size_t)row * Dq + ch * 8);
        }
        if (tid < 32)      cp16(cku + tid * 16, cph + (size_t)bh * Nq + step * 128 + tid * 4);
        else if (tid < 64) cp16(sku + (tid - 32) * 16, sph + (size_t)bh * Nq + step * 128 + (tid - 32) * 4);
        else if (tid < 72) cp16(mku + (tid - 64) * 16, mask + (size_t)b * Nq + step * 128 + (tid - 64) * 16);
        cp_commit();
    };
    issueKV(0, 0);
    issueKV(1, 1);
    cp_wait1();
    __syncthreads();

    const int nw = warp * 16, r = lane >> 2;
    uint32_t qf[4][4];
    #pragma unroll
    for (int kc = 0; kc < 4; kc++)
        ldm_x4(qf[kc], sb + (uint32_t)((nw + (lane & 15)) * 144 + (kc * 16 + ((lane >> 4) << 3)) * 2));
    const float cq0 = cph[(size_t)bh * Nq + n0 + nw + r];
    const float sq0 = sph[(size_t)bh * Nq + n0 + nw + r];
    const float cq1 = cph[(size_t)bh * Nq + n0 + nw + r + 8];
    const float sq1 = sph[(size_t)bh * Nq + n0 + nw + r + 8];

    float O[8][4];
    #pragma unroll
    for (int i = 0; i < 8; i++)
        #pragma unroll
        for (int j = 0; j < 4; j++) O[i][j] = 0.f;
    float mr0 = -1e30f, mr1 = -1e30f, l0 = 0.f, l1 = 0.f;

    const int NSTEP = Nq / 128;     // 16
    for (int c = 0; c < NSTEP; c++) {
        if (c > 0) { cp_wait1(); __syncthreads(); }
        const uint32_t ku = sb + 18432 + (c & 1) * FLASH_STAGE;
        const uint32_t vu = ku + 18432;
        const float* ck = (const float*)(fsm + 18432 + (c & 1) * FLASH_STAGE + 36864);
        const float* sk = ck + 128;
        const unsigned char* mkb = (const unsigned char*)(sk + 128);

        float c_[16][4];
        #pragma unroll
        for (int g = 0; g < 16; g++)
            #pragma unroll
            for (int q = 0; q < 4; q++) c_[g][q] = 0.f;

        #pragma unroll
        for (int kc = 0; kc < 4; kc++) {
            #pragma unroll
            for (int gp = 0; gp < 8; gp++) {
                uint32_t bb[4];
                ldm_x4(bb, ku + (uint32_t)((gp * 16 + ((lane >> 4) << 3) + (lane & 7)) * 144
                                           + (kc * 16 + (((lane >> 3) & 1) << 3)) * 2));
                mma16816(c_[2 * gp],     qf[kc], bb);
                mma16816(c_[2 * gp + 1], qf[kc], bb + 2);
            }
        }

        // harmonic + mask + online softmax
        float mx0 = -1e30f, mx1 = -1e30f;
        #pragma unroll
        for (int g = 0; g < 16; g++) {
            const int cg = g * 8 + ((lane & 3) << 1);
            const float2 cm = *(const float2*)(ck + cg);
            const float2 sv = *(const float2*)(sk + cg);
            float s0 = c_[g][0] * (0.0625f + 0.0625f * (cq0 * cm.x + sq0 * sv.x));
            float s1 = c_[g][1] * (0.0625f + 0.0625f * (cq0 * cm.y + sq0 * sv.y));
            float s2 = c_[g][2] * (0.0625f + 0.0625f * (cq1 * cm.x + sq1 * sv.x));
            float s3 = c_[g][3] * (0.0625f + 0.0625f * (cq1 * cm.y + sq1 * sv.y));
            if (mkb[cg])     { s0 = -1e30f; s2 = -1e30f; }
            if (mkb[cg + 1]) { s1 = -1e30f; s3 = -1e30f; }
            c_[g][0] = s0; c_[g][1] = s1; c_[g][2] = s2; c_[g][3] = s3;
            mx0 = fmaxf(mx0, fmaxf(s0, s1));
            mx1 = fmaxf(mx1, fmaxf(s2, s3));
        }
        mx0 = fmaxf(mx0, __shfl_xor_sync(~0u, mx0, 1));
        mx0 = fmaxf(mx0, __shfl_xor_sync(~0u, mx0, 2));
        mx1 = fmaxf(mx1, __shfl_xor_sync(~0u, mx1, 1));
        mx1 = fmaxf(mx1, __shfl_xor_sync(~0u, mx1, 2));
        const float mn0 = fmaxf(mr0, mx0), mn1 = fmaxf(mr1, mx1);
        const float sc0 = __expf(mr0 - mn0), sc1 = __expf(mr1 - mn1);
        mr0 = mn0; mr1 = mn1;
        l0 *= sc0; l1 *= sc1;
        #pragma unroll
        for (int dg = 0; dg < 8; dg++) {
            O[dg][0] *= sc0; O[dg][1] *= sc0; O[dg][2] *= sc1; O[dg][3] *= sc1;
        }
        #pragma unroll
        for (int g = 0; g < 16; g++) {
            const float p0 = __expf(c_[g][0] - mr0), p1 = __expf(c_[g][1] - mr0);
            const float p2 = __expf(c_[g][2] - mr1), p3 = __expf(c_[g][3] - mr1);
            c_[g][0] = p0; c_[g][1] = p1; c_[g][2] = p2; c_[g][3] = p3;
            l0 += p0 + p1; l1 += p2 + p3;
        }

        // P @ V
        #pragma unroll
        for (int kc2 = 0; kc2 < 8; kc2++) {
            uint32_t a[4];
            a[0] = pack2(c_[2 * kc2][0],     c_[2 * kc2][1]);
            a[1] = pack2(c_[2 * kc2][2],     c_[2 * kc2][3]);
            a[2] = pack2(c_[2 * kc2 + 1][0], c_[2 * kc2 + 1][1]);
            a[3] = pack2(c_[2 * kc2 + 1][2], c_[2 * kc2 + 1][3]);
            #pragma unroll
            for (int dgp = 0; dgp < 4; dgp++) {
                uint32_t bb[4];
                ldm_x4_t(bb, vu + (uint32_t)((kc2 * 16 + (lane & 15)) * 144
                                             + (dgp * 16 + ((lane >> 4) << 3)) * 2));
                mma16816(O[2 * dgp],     a, bb);
                mma16816(O[2 * dgp + 1], a, bb + 2);
            }
        }
        __syncthreads();
        if (c + 2 < NSTEP) issueKV(c + 2, c & 1);
    }

    l0 += __shfl_xor_sync(~0u, l0, 1); l0 += __shfl_xor_sync(~0u, l0, 2);
    l1 += __shfl_xor_sync(~0u, l1, 1); l1 += __shfl_xor_sync(~0u, l1, 2);
    const float i0 = 1.f / l0, i1 = 1.f / l1;
    const size_t row0 = (size_t)(b * Nq + n0 + nw + r) * Dq + hh * DHq;
    const size_t row1 = row0 + 8 * Dq;
    #pragma unroll
    for (int dg = 0; dg < 8; dg++) {
        const int d = dg * 8 + ((lane & 3) << 1);
        *(__nv_bfloat162*)(Mhi + row0 + d) =
            __float22bfloat162_rn(make_float2(O[dg][0] * i0, O[dg][1] * i0));
        *(__nv_bfloat162*)(Mhi + row1 + d) =
            __float22bfloat162_rn(make_float2(O[dg][2] * i1, O[dg][3] * i1));
    }
}

// ---------------- weight transpose + bf16 split -------------------------------
__global__ void wtrans_kernel(const float* __restrict__ W, __nv_bfloat16* __restrict__ T_hi,
                              __nv_bfloat16* __restrict__ T_lo, int K, int Nc) {
    __shared__ float t[32][33];
    const int k0 = blockIdx.y * 32, n0 = blockIdx.x * 32;
    const int tx = threadIdx.x, ty = threadIdx.y;
    #pragma unroll
    for (int i = ty; i < 32; i += 8) t[i][tx] = W[(size_t)(k0 + i) * Nc + n0 + tx];
    __syncthreads();
    #pragma unroll
    for (int i = ty; i < 32; i += 8) {
        const float v = t[tx][i];
        const __nv_bfloat16 hi = __float2bfloat16(v);
        T_hi[(size_t)(n0 + i) * K + k0 + tx] = hi;
        T_lo[(size_t)(n0 + i) * K + k0 + tx] = __float2bfloat16(v - __bfloat162float(hi));
    }
}

__global__ void fsplit_kernel(const float* __restrict__ X, __nv_bfloat16* __restrict__ hi,
                              __nv_bfloat16* __restrict__ lo, int n) {
    const int i = blockIdx.x * 256 + threadIdx.x;
    if (i < n) {
        const float v = X[i];
        const __nv_bfloat16 h = __float2bfloat16(v);
        hi[i] = h;
        lo[i] = __float2bfloat16(v - __bfloat162float(h));
    }
}

// ---------------- 8-wide projection + cos/sin / phase update ------------------
__global__ void proj8_kernel(const float* __restrict__ X, const float* __restrict__ W8,
                             const float* __restrict__ b8, const float* __restrict__ phases,
                             float* __restrict__ out, float* __restrict__ cph,
                             float* __restrict__ sph, int mode) {
    __shared__ float hs[Dq];
    const int row = blockIdx.x;
    const int tid = threadIdx.x;
    hs[tid]       = X[(size_t)row * Dq + tid];
    hs[tid + 256] = X[(size_t)row * Dq + tid + 256];
    __syncthreads();
    const int w = tid >> 5, lane = tid & 31;
    float s = 0.f;
    #pragma unroll
    for (int kk = lane; kk < Dq; kk += 32) s += hs[kk] * W8[kk * Hq + w];
    #pragma unroll
    for (int o = 16; o; o >>= 1) s += __shfl_xor_sync(0xffffffffu, s, o);
    if (lane == 0) {
        s += b8[w];
        if (mode) {
            out[(size_t)row * Hq + w] = phases[(size_t)row * Hq + w] + 0.31415926535897932f * tanhf(s);
        } else {
            out[(size_t)row * Hq + w] = s;
            const int b = row >> 11, n = row & 2047;
            cph[(size_t)(b * Hq + w) * Nq + n] = cosf(s);
            sph[(size_t)(b * Hq + w) * Nq + n] = sinf(s);
        }
    }
}

// ---------------- residual add + LayerNorm (+ optional split out) -------------
__global__ void addln_kernel(const float* __restrict__ X, const float* __restrict__ Y,
                             const float* __restrict__ g, const float* __restrict__ be,
                             float* __restrict__ out,
                             __nv_bfloat16* __restrict__ ohi, __nv_bfloat16* __restrict__ olo) {
    __shared__ float red[256];
    const size_t row = blockIdx.x;
    const int tid = threadIdx.x;
    float a0 = X[row * Dq + tid]       + Y[row * Dq + tid];
    float a1 = X[row * Dq + tid + 256] + Y[row * Dq + tid + 256];
    red[tid] = a0 + a1; __syncthreads();
    #pragma unroll
    for (int o = 128; o; o >>= 1) { if (tid < o) red[tid] += red[tid + o]; __syncthreads(); }
    const float mu = red[0] * (1.f / Dq); __syncthreads();
    const float d0 = a0 - mu, d1 = a1 - mu;
    red[tid] = d0 * d0 + d1 * d1; __syncthreads();
    #pragma unroll
    for (int o = 128; o; o >>= 1) { if (tid < o) red[tid] += red[tid + o]; __syncthreads(); }
    const float rstd = rsqrtf(red[0] * (1.f / Dq) + 1e-5f);
    const float r0 = d0 * rstd * g[tid]       + be[tid];
    const float r1 = d1 * rstd * g[tid + 256] + be[tid + 256];
    out[row * Dq + tid]       = r0;
    out[row * Dq + tid + 256] = r1;
    if (ohi) {
        const __nv_bfloat16 h0 = __float2bfloat16(r0);
        const __nv_bfloat16 h1b = __float2bfloat16(r1);
        ohi[row * Dq + tid]       = h0;
        ohi[row * Dq + tid + 256] = h1b;
        olo[row * Dq + tid]       = __float2bfloat16(r0 - __bfloat162float(h0));
        olo[row * Dq + tid + 256] = __float2bfloat16(r1 - __bfloat162float(h1b));
    }
}

// ---------------- delta = mean_row ||h2 - h|| ---------------------------------
__global__ void rownorm_kernel(const float* __restrict__ h2, const float* __restrict__ h,
                               float* __restrict__ rn) {
    __shared__ float red[256];
    const size_t row = blockIdx.x;
    const int tid = threadIdx.x;
    float d0 = h2[row * Dq + tid]       - h[row * Dq + tid];
    float d1 = h2[row * Dq + tid + 256] - h[row * Dq + tid + 256];
    red[tid] = d0 * d0 + d1 * d1; __syncthreads();
    #pragma unroll
    for (int o = 128; o; o >>= 1) { if (tid < o) red[tid] += red[tid + o]; __syncthreads(); }
    if (tid == 0) rn[row] = sqrtf(red[0]);
}

__global__ void delta_kernel(const float* __restrict__ rn, float* __restrict__ out) {
    __shared__ float red[256];
    const int tid = threadIdx.x;
    float s = 0.f;
    for (int i = tid; i < ROWS; i += 256) s += rn[i];
    red[tid] = s; __syncthreads();
    #pragma unroll
    for (int o = 128; o; o >>= 1) { if (tid < o) red[tid] += red[tid + o]; __syncthreads(); }
    if (tid == 0) out[0] = red[0] * (1.f / ROWS);
}

// ---------------- launch ------------------------------------------------------
extern "C" void kernel_launch(void* const* d_in, const int* in_sizes, int n_in,
                              void* d_out, int out_size) {
    const float* h      = (const float*)d_in[0];
    const float* phases = (const float*)d_in[1];
    const unsigned char* mask = (const unsigned char*)d_in[2];
    const float* Wq  = (const float*)d_in[3];
    const float* Wk  = (const float*)d_in[4];
    const float* Wp  = (const float*)d_in[5];
    const float* bp  = (const float*)d_in[6];
    const float* Wv  = (const float*)d_in[7];
    const float* Wo  = (const float*)d_in[8];
    const float* W1  = (const float*)d_in[9];
    const float* b1  = (const float*)d_in[10];
    const float* W2  = (const float*)d_in[11];
    const float* b2  = (const float*)d_in[12];
    const float* g1  = (const float*)d_in[13];
    const float* be1 = (const float*)d_in[14];
    const float* g2  = (const float*)d_in[15];
    const float* be2 = (const float*)d_in[16];
    const float* Wph = (const float*)d_in[17];
    const float* bph = (const float*)d_in[18];

    float* out_h2     = (float*)d_out;
    float* out_phases = out_h2 + (size_t)ROWS * Dq;
    float* out_delta  = out_phases + (size_t)ROWS * Hq;

    float *ph, *cphp, *sphp, *msgO, *h1, *ffn2, *rn;
    __nv_bfloat16 *Qb, *Kb, *Vb, *hhi, *hlo, *h1hi, *h1lo, *mhi, *f1hi, *f1lo;
    __nv_bfloat16 *WqTh, *WqTl, *WkTh, *WkTl, *WvTh, *WvTl, *WoTh, *WoTl, *W1Th, *W1Tl, *W2Th, *W2Tl;
    cudaGetSymbolAddress((void**)&ph, g_ph);
    cudaGetSymbolAddress((void**)&cphp, g_cph); cudaGetSymbolAddress((void**)&sphp, g_sph);
    cudaGetSymbolAddress((void**)&msgO, g_msgO);
    cudaGetSymbolAddress((void**)&h1, g_h1);    cudaGetSymbolAddress((void**)&ffn2, g_ffn2);
    cudaGetSymbolAddress((void**)&rn, g_rn);
    cudaGetSymbolAddress((void**)&Qb, g_Qb);    cudaGetSymbolAddress((void**)&Kb, g_Kb);
    cudaGetSymbolAddress((void**)&Vb, g_Vb);
    cudaGetSymbolAddress((void**)&hhi, g_h_hi); cudaGetSymbolAddress((void**)&hlo, g_h_lo);
    cudaGetSymbolAddress((void**)&h1hi, g_h1_hi); cudaGetSymbolAddress((void**)&h1lo, g_h1_lo);
    cudaGetSymbolAddress((void**)&mhi, g_msg_hi);
    cudaGetSymbolAddress((void**)&f1hi, g_ffn1_hi); cudaGetSymbolAddress((void**)&f1lo, g_ffn1_lo);
    cudaGetSymbolAddress((void**)&WqTh, g_WqT_hi); cudaGetSymbolAddress((void**)&WqTl, g_WqT_lo);
    cudaGetSymbolAddress((void**)&WkTh, g_WkT_hi); cudaGetSymbolAddress((void**)&WkTl, g_WkT_lo);
    cudaGetSymbolAddress((void**)&WvTh, g_WvT_hi); cudaGetSymbolAddress((void**)&WvTl, g_WvT_lo);
    cudaGetSymbolAddress((void**)&WoTh, g_WoT_hi); cudaGetSymbolAddress((void**)&WoTl, g_WoT_lo);
    cudaGetSymbolAddress((void**)&W1Th, g_W1T_hi); cudaGetSymbolAddress((void**)&W1Tl, g_W1T_lo);
    cudaGetSymbolAddress((void**)&W2Th, g_W2T_hi); cudaGetSymbolAddress((void**)&W2Tl, g_W2T_lo);

    cudaFuncSetAttribute(flash_kernel, cudaFuncAttributeMaxDynamicSharedMemorySize, FLASH_SMEM);

    const dim3 tb(32, 8);
    wtrans_kernel<<<dim3(Dq / 32, Dq / 32), tb>>>(Wq, WqTh, WqTl, Dq, Dq);
    wtrans_kernel<<<dim3(Dq / 32, Dq / 32), tb>>>(Wk, WkTh, WkTl, Dq, Dq);
    wtrans_kernel<<<dim3(Dq / 32, Dq / 32), tb>>>(Wv, WvTh, WvTl, Dq, Dq);
    wtrans_kernel<<<dim3(Dq / 32, Dq / 32), tb>>>(Wo, WoTh, WoTl, Dq, Dq);
    wtrans_kernel<<<dim3(Fq / 32, Dq / 32), tb>>>(W1, W1Th, W1Tl, Dq, Fq);
    wtrans_kernel<<<dim3(Dq / 32, Fq / 32), tb>>>(W2, W2Th, W2Tl, Fq, Dq);
    fsplit_kernel<<<(ROWS * Dq + 255) / 256, 256>>>(h, hhi, hlo, ROWS * Dq);

    const dim3 gDD(Dq / 128, ROWS / 128);
    const dim3 gDF(Fq / 128, ROWS / 128);

    // projections -> bf16 (1-term)
    tgemm_kernel<<<gDD, 256>>>(hhi, nullptr, WqTh, nullptr, nullptr, nullptr, Qb, nullptr, Dq, Dq, 8, 1);
    tgemm_kernel<<<gDD, 256>>>(hhi, nullptr, WkTh, nullptr, nullptr, nullptr, Kb, nullptr, Dq, Dq, 8, 1);
    tgemm_kernel<<<gDD, 256>>>(hhi, nullptr, WvTh, nullptr, nullptr, nullptr, Vb, nullptr, Dq, Dq, 8, 1);
    proj8_kernel<<<ROWS, 256>>>(h, Wp, bp, nullptr, ph, cphp, sphp, 0);

    // fused flash attention
    flash_kernel<<<dim3(Nq / 128, BHq), 256, FLASH_SMEM>>>(Qb, Kb, Vb, cphp, sphp, mask, mhi);

    tgemm_kernel<<<gDD, 256>>>(mhi, nullptr, WoTh, nullptr, nullptr, msgO, nullptr, nullptr, Dq, Dq, 0, 1);
    addln_kernel<<<ROWS, 256>>>(h, msgO, g1, be1, h1, h1hi, h1lo);

    // FFN (3-term split)
    tgemm_kernel<<<gDF, 256>>>(h1hi, h1lo, W1Th, W1Tl, b1, nullptr, f1hi, f1lo, Dq, Fq, 7, 3);
    tgemm_kernel<<<gDD, 256>>>(f1hi, f1lo, W2Th, W2Tl, b2, ffn2, nullptr, nullptr, Fq, Dq, 1, 3);
    addln_kernel<<<ROWS, 256>>>(h1, ffn2, g2, be2, out_h2, nullptr, nullptr);

    // phase update + delta
    proj8_kernel<<<ROWS, 256>>>(out_h2, Wph, bph, phases, out_phases, nullptr, nullptr, 1);
    rownorm_kernel<<<ROWS, 256>>>(out_h2, h, rn);
    delta_kernel<<<1, 256>>>(rn, out_delta);
}

// round 5
// speedup vs baseline: 5.2109x; 1.1171x over previous
#include <cuda_runtime.h>
#include <cuda_bf16.h>
#include <math.h>
#include <stdint.h>

#define Bq 2
#define Nq 2048
#define Dq 512
#define Hq 8
#define Fq 2048
#define DHq 64
#define ROWS (Bq*Nq)            // 4096
#define BHq (Bq*Hq)             // 16

// ---------------- scratch (static device globals) ---------------------------
__device__ float g_ph[ROWS*Hq];
__device__ float g_cph[BHq*Nq];
__device__ float g_sph[BHq*Nq];
__device__ float g_msgO[ROWS*Dq];
__device__ float g_h1[ROWS*Dq];
__device__ float g_ffn2[ROWS*Dq];
__device__ float g_rn[ROWS];

__device__ __nv_bfloat16 g_Qb[ROWS*Dq], g_Kb[ROWS*Dq], g_Vb[ROWS*Dq];
__device__ __nv_bfloat16 g_h_hi[ROWS*Dq],   g_h_lo[ROWS*Dq];
__device__ __nv_bfloat16 g_h1_hi[ROWS*Dq],  g_h1_lo[ROWS*Dq];
__device__ __nv_bfloat16 g_msg_hi[ROWS*Dq];
__device__ __nv_bfloat16 g_ffn1_hi[(size_t)ROWS*Fq], g_ffn1_lo[(size_t)ROWS*Fq];
__device__ __nv_bfloat16 g_WqT_hi[Dq*Dq], g_WqT_lo[Dq*Dq];
__device__ __nv_bfloat16 g_WkT_hi[Dq*Dq], g_WkT_lo[Dq*Dq];
__device__ __nv_bfloat16 g_WvT_hi[Dq*Dq], g_WvT_lo[Dq*Dq];
__device__ __nv_bfloat16 g_WoT_hi[Dq*Dq], g_WoT_lo[Dq*Dq];
__device__ __nv_bfloat16 g_W1T_hi[(size_t)Fq*Dq], g_W1T_lo[(size_t)Fq*Dq];
__device__ __nv_bfloat16 g_W2T_hi[(size_t)Dq*Fq], g_W2T_lo[(size_t)Dq*Fq];

// ---------------- PTX helpers -----------------------------------------------
__device__ __forceinline__ uint32_t smem_u32(const void* p) {
    return (uint32_t)__cvta_generic_to_shared(p);
}
__device__ __forceinline__ void cp16(uint32_t s, const void* g) {
    asm volatile("cp.async.cg.shared.global [%0], [%1], 16;" :: "r"(s), "l"(g));
}
__device__ __forceinline__ void cp_commit() { asm volatile("cp.async.commit_group;" ::: "memory"); }
__device__ __forceinline__ void cp_wait0()  { asm volatile("cp.async.wait_group 0;" ::: "memory"); }
__device__ __forceinline__ void cp_wait1()  { asm volatile("cp.async.wait_group 1;" ::: "memory"); }

__device__ __forceinline__ void ldm_x4(uint32_t* r, uint32_t addr) {
    asm volatile("ldmatrix.sync.aligned.m8n8.x4.shared.b16 {%0,%1,%2,%3}, [%4];"
                 : "=r"(r[0]), "=r"(r[1]), "=r"(r[2]), "=r"(r[3]) : "r"(addr));
}
__device__ __forceinline__ void ldm_x4_t(uint32_t* r, uint32_t addr) {
    asm volatile("ldmatrix.sync.aligned.m8n8.x4.trans.shared.b16 {%0,%1,%2,%3}, [%4];"
                 : "=r"(r[0]), "=r"(r[1]), "=r"(r[2]), "=r"(r[3]) : "r"(addr));
}
__device__ __forceinline__ void mma16816(float* c, const uint32_t* a, const uint32_t* b) {
    asm volatile("mma.sync.aligned.m16n8k16.row.col.f32.bf16.bf16.f32 "
                 "{%0,%1,%2,%3}, {%4,%5,%6,%7}, {%8,%9}, {%0,%1,%2,%3};"
                 : "+f"(c[0]), "+f"(c[1]), "+f"(c[2]), "+f"(c[3])
                 : "r"(a[0]), "r"(a[1]), "r"(a[2]), "r"(a[3]), "r"(b[0]), "r"(b[1]));
}
__device__ __forceinline__ uint32_t pack2(float x, float y) {
    __nv_bfloat162 t = __float22bfloat162_rn(make_float2(x, y));
    return *(uint32_t*)&t;
}

// ---------------- HMMA bf16 GEMM: C = A(MxK) @ BT(NxK)^T ---------------------
// TERMS=1: C = Ahi@Bhi^T ; TERMS=3: + Ahi@Blo^T + Alo@Bhi^T (all tiles loaded once/chunk)
// epi bit0: +bias ; bit1: GELU ; bit2: bf16 hi/lo out ; bit3: plain bf16 out
#define TSTR 40
#define TILE_B (128 * TSTR * 2)         // 10240 bytes per tile
template<int TERMS>
__global__ __launch_bounds__(256) void tgemm_kernel(
    const __nv_bfloat16* __restrict__ A_hi, const __nv_bfloat16* __restrict__ A_lo,
    const __nv_bfloat16* __restrict__ B_hi, const __nv_bfloat16* __restrict__ B_lo,
    const float* __restrict__ bias,
    float* __restrict__ Cf, __nv_bfloat16* __restrict__ C_hi, __nv_bfloat16* __restrict__ C_lo,
    int K, int Nc, int epi)
{
    extern __shared__ __align__(128) unsigned char dsm[];
    const int NT = (TERMS == 3) ? 4 : 2;        // tiles per stage
    const uint32_t stg = NT * TILE_B;
    const uint32_t sb = smem_u32(dsm);
    const int tid = threadIdx.x;
    const int warp = tid >> 5, lane = tid & 31;
    const int wm = warp >> 1, wn = warp & 1;
    const int bm = blockIdx.y * 128, bn = blockIdx.x * 128;

    const int NCH = K >> 5;
    const int lrow = tid >> 2, lch = (tid & 3) << 3;

    float acc[2][8][4];
    #pragma unroll
    for (int i = 0; i < 2; i++)
        #pragma unroll
        for (int j = 0; j < 8; j++)
            #pragma unroll
            for (int q = 0; q < 4; q++) acc[i][j][q] = 0.f;

    auto issue = [&](int c, int s) {
        const int kc = c << 5;
        const uint32_t base = sb + s * stg;
        #pragma unroll
        for (int i = 0; i < 2; i++) {
            const int row = lrow + i * 64;
            const uint32_t so = (uint32_t)(row * TSTR + lch) * 2;
            cp16(base + so,              A_hi + (size_t)(bm + row) * K + kc + lch);
            cp16(base + TILE_B + so,     B_hi + (size_t)(bn + row) * K + kc + lch);
            if (TERMS == 3) {
                cp16(base + 2 * TILE_B + so, A_lo + (size_t)(bm + row) * K + kc + lch);
                cp16(base + 3 * TILE_B + so, B_lo + (size_t)(bn + row) * K + kc + lch);
            }
        }
        cp_commit();
    };

    issue(0, 0);
    for (int c = 0; c < NCH; c++) {
        const int s = c & 1;
        cp_wait0();
        __syncthreads();
        if (c + 1 < NCH) issue(c + 1, s ^ 1);
        const uint32_t base = sb + s * stg;
        #pragma unroll
        for (int ks = 0; ks < 2; ks++) {
            const uint32_t arow = (uint32_t)((wm * 32 + (lane & 15)) * TSTR
                                             + ks * 16 + ((lane >> 4) << 3)) * 2;
            const uint32_t brow = (uint32_t)((wn * 64 + ((lane >> 4) << 3) + (lane & 7)) * TSTR
                                             + ks * 16 + (((lane >> 3) & 1) << 3)) * 2;
            uint32_t aH[2][4], bH[4][4];
            #pragma unroll
            for (int mt = 0; mt < 2; mt++)
                ldm_x4(aH[mt], base + arow + (uint32_t)(mt * 16 * TSTR) * 2);
            #pragma unroll
            for (int nt4 = 0; nt4 < 4; nt4++)
                ldm_x4(bH[nt4], base + TILE_B + brow + (uint32_t)(nt4 * 16 * TSTR) * 2);
            #pragma unroll
            for (int mt = 0; mt < 2; mt++)
                #pragma unroll
                for (int nt = 0; nt < 8; nt++)
                    mma16816(acc[mt][nt], aH[mt], &bH[nt >> 1][(nt & 1) * 2]);
            if (TERMS == 3) {
                uint32_t bL[4][4];
                #pragma unroll
                for (int nt4 = 0; nt4 < 4; nt4++)
                    ldm_x4(bL[nt4], base + 3 * TILE_B + brow + (uint32_t)(nt4 * 16 * TSTR) * 2);
                #pragma unroll
                for (int mt = 0; mt < 2; mt++)
                    #pragma unroll
                    for (int nt = 0; nt < 8; nt++)
                        mma16816(acc[mt][nt], aH[mt], &bL[nt >> 1][(nt & 1) * 2]);
                uint32_t aL[2][4];
                #pragma unroll
                for (int mt = 0; mt < 2; mt++)
                    ldm_x4(aL[mt], base + 2 * TILE_B + arow + (uint32_t)(mt * 16 * TSTR) * 2);
                #pragma unroll
                for (int mt = 0; mt < 2; mt++)
                    #pragma unroll
                    for (int nt = 0; nt < 8; nt++)
                        mma16816(acc[mt][nt], aL[mt], &bH[nt >> 1][(nt & 1) * 2]);
            }
        }
        __syncthreads();
    }

    #pragma unroll
    for (int mt = 0; mt < 2; mt++) {
        const int r0 = bm + wm * 32 + mt * 16 + (lane >> 2);
        #pragma unroll
        for (int nt = 0; nt < 8; nt++) {
            const int gn = bn + wn * 64 + nt * 8 + ((lane & 3) << 1);
            #pragma unroll
            for (int half = 0; half < 2; half++) {
                const int row = r0 + half * 8;
                float v0 = acc[mt][nt][half * 2 + 0];
                float v1 = acc[mt][nt][half * 2 + 1];
                if (epi & 1) { v0 += bias[gn]; v1 += bias[gn + 1]; }
                if (epi & 2) {
                    v0 = 0.5f * v0 * (1.f + erff(v0 * 0.7071067811865475f));
                    v1 = 0.5f * v1 * (1.f + erff(v1 * 0.7071067811865475f));
                }
                const size_t idx = (size_t)row * Nc + gn;
                if (epi & 4) {
                    const __nv_bfloat16 h0 = __float2bfloat16(v0);
                    const __nv_bfloat16 h1 = __float2bfloat16(v1);
                    C_hi[idx] = h0;      C_hi[idx + 1] = h1;
                    C_lo[idx] = __float2bfloat16(v0 - __bfloat162float(h0));
                    C_lo[idx + 1] = __float2bfloat16(v1 - __bfloat162float(h1));
                } else if (epi & 8) {
                    *(__nv_bfloat162*)(C_hi + idx) =
                        __float22bfloat162_rn(make_float2(v0, v1));
                } else {
                    *(float2*)(Cf + idx) = make_float2(v0, v1);
                }
            }
        }
    }
}

// ---------------- fused flash attention (bf16 HMMA) --------------------------
#define FLASH_STAGE 38016
#define FLASH_SMEM (18432 + 2 * FLASH_STAGE)
__global__ __launch_bounds__(256) void flash_kernel(
    const __nv_bfloat16* __restrict__ Qb, const __nv_bfloat16* __restrict__ Kb,
    const __nv_bfloat16* __restrict__ Vb,
    const float* __restrict__ cph, const float* __restrict__ sph,
    const unsigned char* __restrict__ mask,
    __nv_bfloat16* __restrict__ Mhi)
{
    extern __shared__ __align__(128) unsigned char fsm[];
    const int tid = threadIdx.x, warp = tid >> 5, lane = tid & 31;
    const int bh = blockIdx.y, b = bh >> 3, hh = bh & 7;
    const int n0 = blockIdx.x * 128;
    const uint32_t sb = smem_u32(fsm);

    const __nv_bfloat16* gQ = Qb + ((size_t)b * Nq + n0) * Dq + hh * DHq;
    #pragma unroll
    for (int i = 0; i < 4; i++) {
        const int id = tid + i * 256, row = id >> 3, ch = id & 7;
        cp16(sb + row * 144 + ch * 16, gQ + (size_t)row * Dq + ch * 8);
    }
    cp_commit();

    auto issueKV = [&](int step, int s) {
        const uint32_t ku = sb + 18432 + s * FLASH_STAGE;
        const uint32_t vu = ku + 18432, cku = ku + 36864, sku = ku + 37376, mku = ku + 37888;
        const __nv_bfloat16* gK = Kb + ((size_t)b * Nq + step * 128) * Dq + hh * DHq;
        const __nv_bfloat16* gV = Vb + ((size_t)b * Nq + step * 128) * Dq + hh * DHq;
        #pragma unroll
        for (int i = 0; i < 4; i++) {
            const int id = tid + i * 256, row = id >> 3, ch = id & 7;
            cp16(ku + row * 144 + ch * 16, gK + (size_t)row * Dq + ch * 8);
            cp16(vu + row * 144 + ch * 16, gV + (size_t)row * Dq + ch * 8);
        }
        if (tid < 32)      cp16(cku + tid * 16, cph + (size_t)bh * Nq + step * 128 + tid * 4);
        else if (tid < 64) cp16(sku + (tid - 32) * 16, sph + (size_t)bh * Nq + step * 128 + (tid - 32) * 4);
        else if (tid < 72) cp16(mku + (tid - 64) * 16, mask + (size_t)b * Nq + step * 128 + (tid - 64) * 16);
        cp_commit();
    };
    issueKV(0, 0);
    issueKV(1, 1);
    cp_wait1();
    __syncthreads();

    const int nw = warp * 16, r = lane >> 2;
    uint32_t qf[4][4];
    #pragma unroll
    for (int kc = 0; kc < 4; kc++)
        ldm_x4(qf[kc], sb + (uint32_t)((nw + (lane & 15)) * 144 + (kc * 16 + ((lane >> 4) << 3)) * 2));
    const float cq0 = cph[(size_t)bh * Nq + n0 + nw + r];
    const float sq0 = sph[(size_t)bh * Nq + n0 + nw + r];
    const float cq1 = cph[(size_t)bh * Nq + n0 + nw + r + 8];
    const float sq1 = sph[(size_t)bh * Nq + n0 + nw + r + 8];

    float O[8][4];
    #pragma unroll
    for (int i = 0; i < 8; i++)
        #pragma unroll
        for (int j = 0; j < 4; j++) O[i][j] = 0.f;
    float mr0 = -1e30f, mr1 = -1e30f, l0 = 0.f, l1 = 0.f;

    const int NSTEP = Nq / 128;
    for (int c = 0; c < NSTEP; c++) {
        if (c > 0) { cp_wait1(); __syncthreads(); }
        const uint32_t ku = sb + 18432 + (c & 1) * FLASH_STAGE;
        const uint32_t vu = ku + 18432;
        const float* ck = (const float*)(fsm + 18432 + (c & 1) * FLASH_STAGE + 36864);
        const float* sk = ck + 128;
        const unsigned char* mkb = (const unsigned char*)(sk + 128);

        float c_[16][4];
        #pragma unroll
        for (int g = 0; g < 16; g++)
            #pragma unroll
            for (int q = 0; q < 4; q++) c_[g][q] = 0.f;

        #pragma unroll
        for (int kc = 0; kc < 4; kc++) {
            #pragma unroll
            for (int gp = 0; gp < 8; gp++) {
                uint32_t bb[4];
                ldm_x4(bb, ku + (uint32_t)((gp * 16 + ((lane >> 4) << 3) + (lane & 7)) * 144
                                           + (kc * 16 + (((lane >> 3) & 1) << 3)) * 2));
                mma16816(c_[2 * gp],     qf[kc], bb);
                mma16816(c_[2 * gp + 1], qf[kc], bb + 2);
            }
        }

        float mx0 = -1e30f, mx1 = -1e30f;
        #pragma unroll
        for (int g = 0; g < 16; g++) {
            const int cg = g * 8 + ((lane & 3) << 1);
            const float2 cm = *(const float2*)(ck + cg);
            const float2 sv = *(const float2*)(sk + cg);
            float s0 = c_[g][0] * (0.0625f + 0.0625f * (cq0 * cm.x + sq0 * sv.x));
            float s1 = c_[g][1] * (0.0625f + 0.0625f * (cq0 * cm.y + sq0 * sv.y));
            float s2 = c_[g][2] * (0.0625f + 0.0625f * (cq1 * cm.x + sq1 * sv.x));
            float s3 = c_[g][3] * (0.0625f + 0.0625f * (cq1 * cm.y + sq1 * sv.y));
            if (mkb[cg])     { s0 = -1e30f; s2 = -1e30f; }
            if (mkb[cg + 1]) { s1 = -1e30f; s3 = -1e30f; }
            c_[g][0] = s0; c_[g][1] = s1; c_[g][2] = s2; c_[g][3] = s3;
            mx0 = fmaxf(mx0, fmaxf(s0, s1));
            mx1 = fmaxf(mx1, fmaxf(s2, s3));
        }
        mx0 = fmaxf(mx0, __shfl_xor_sync(~0u, mx0, 1));
        mx0 = fmaxf(mx0, __shfl_xor_sync(~0u, mx0, 2));
        mx1 = fmaxf(mx1, __shfl_xor_sync(~0u, mx1, 1));
        mx1 = fmaxf(mx1, __shfl_xor_sync(~0u, mx1, 2));
        const float mn0 = fmaxf(mr0, mx0), mn1 = fmaxf(mr1, mx1);
        const float sc0 = __expf(mr0 - mn0), sc1 = __expf(mr1 - mn1);
        mr0 = mn0; mr1 = mn1;
        l0 *= sc0; l1 *= sc1;
        #pragma unroll
        for (int dg = 0; dg < 8; dg++) {
            O[dg][0] *= sc0; O[dg][1] *= sc0; O[dg][2] *= sc1; O[dg][3] *= sc1;
        }
        #pragma unroll
        for (int g = 0; g < 16; g++) {
            const float p0 = __expf(c_[g][0] - mr0), p1 = __expf(c_[g][1] - mr0);
            const float p2 = __expf(c_[g][2] - mr1), p3 = __expf(c_[g][3] - mr1);
            c_[g][0] = p0; c_[g][1] = p1; c_[g][2] = p2; c_[g][3] = p3;
            l0 += p0 + p1; l1 += p2 + p3;
        }

        #pragma unroll
        for (int kc2 = 0; kc2 < 8; kc2++) {
            uint32_t a[4];
            a[0] = pack2(c_[2 * kc2][0],     c_[2 * kc2][1]);
            a[1] = pack2(c_[2 * kc2][2],     c_[2 * kc2][3]);
            a[2] = pack2(c_[2 * kc2 + 1][0], c_[2 * kc2 + 1][1]);
            a[3] = pack2(c_[2 * kc2 + 1][2], c_[2 * kc2 + 1][3]);
            #pragma unroll
            for (int dgp = 0; dgp < 4; dgp++) {
                uint32_t bb[4];
                ldm_x4_t(bb, vu + (uint32_t)((kc2 * 16 + (lane & 15)) * 144
                                             + (dgp * 16 + ((lane >> 4) << 3)) * 2));
                mma16816(O[2 * dgp],     a, bb);
                mma16816(O[2 * dgp + 1], a, bb + 2);
            }
        }
        __syncthreads();
        if (c + 2 < NSTEP) issueKV(c + 2, c & 1);
    }

    l0 += __shfl_xor_sync(~0u, l0, 1); l0 += __shfl_xor_sync(~0u, l0, 2);
    l1 += __shfl_xor_sync(~0u, l1, 1); l1 += __shfl_xor_sync(~0u, l1, 2);
    const float i0 = 1.f / l0, i1 = 1.f / l1;
    const size_t row0 = (size_t)(b * Nq + n0 + nw + r) * Dq + hh * DHq;
    const size_t row1 = row0 + 8 * Dq;
    #pragma unroll
    for (int dg = 0; dg < 8; dg++) {
        const int d = dg * 8 + ((lane & 3) << 1);
        *(__nv_bfloat162*)(Mhi + row0 + d) =
            __float22bfloat162_rn(make_float2(O[dg][0] * i0, O[dg][1] * i0));
        *(__nv_bfloat162*)(Mhi + row1 + d) =
            __float22bfloat162_rn(make_float2(O[dg][2] * i1, O[dg][3] * i1));
    }
}

// ---------------- fused weight transpose+split (all 6 weights, one launch) ---
__device__ __forceinline__ void wtile(const float* __restrict__ W, __nv_bfloat16* __restrict__ Th,
                                      __nv_bfloat16* __restrict__ Tl, int K, int Nc,
                                      int k0, int n0, int tx, int ty, float t[32][33]) {
    #pragma unroll
    for (int i = ty; i < 32; i += 8) t[i][tx] = W[(size_t)(k0 + i) * Nc + n0 + tx];
    __syncthreads();
    #pragma unroll
    for (int i = ty; i < 32; i += 8) {
        const float v = t[tx][i];
        const __nv_bfloat16 hi = __float2bfloat16(v);
        Th[(size_t)(n0 + i) * K + k0 + tx] = hi;
        Tl[(size_t)(n0 + i) * K + k0 + tx] = __float2bfloat16(v - __bfloat162float(hi));
    }
}

__global__ void wtrans_all_kernel(
    const float* Wq, const float* Wk, const float* Wv, const float* Wo,
    const float* W1, const float* W2,
    __nv_bfloat16* qh, __nv_bfloat16* ql, __nv_bfloat16* kh, __nv_bfloat16* kl,
    __nv_bfloat16* vh, __nv_bfloat16* vl, __nv_bfloat16* oh, __nv_bfloat16* ol,
    __nv_bfloat16* w1h, __nv_bfloat16* w1l, __nv_bfloat16* w2h, __nv_bfloat16* w2l)
{
    __shared__ float t[32][33];
    const int tx = threadIdx.x, ty = threadIdx.y;
    int id = blockIdx.x;
    if (id < 1024) {                        // Wq/Wk/Wv/Wo: 256 tiles each (16x16)
        const int w = id >> 8, tl = id & 255;
        const int n0 = (tl & 15) * 32, k0 = (tl >> 4) * 32;
        const float* W = (w == 0) ? Wq : (w == 1) ? Wk : (w == 2) ? Wv : Wo;
        __nv_bfloat16* Th = (w == 0) ? qh : (w == 1) ? kh : (w == 2) ? vh : oh;
        __nv_bfloat16* Tl = (w == 0) ? ql : (w == 1) ? kl : (w == 2) ? vl : ol;
        wtile(W, Th, Tl, Dq, Dq, k0, n0, tx, ty, t);
    } else if (id < 2048) {                 // W1: 512x2048, tiles 16(k) x 64(n)
        const int tl = id - 1024;
        const int n0 = (tl & 63) * 32, k0 = (tl >> 6) * 32;
        wtile(W1, w1h, w1l, Dq, Fq, k0, n0, tx, ty, t);
    } else {                                // W2: 2048x512, tiles 64(k) x 16(n)
        const int tl = id - 2048;
        const int n0 = (tl & 15) * 32, k0 = (tl >> 4) * 32;
        wtile(W2, w2h, w2l, Fq, Dq, k0, n0, tx, ty, t);
    }
}

__global__ void fsplit_kernel(const float* __restrict__ X, __nv_bfloat16* __restrict__ hi,
                              __nv_bfloat16* __restrict__ lo, int n) {
    const int i = blockIdx.x * 256 + threadIdx.x;
    if (i < n) {
        const float v = X[i];
        const __nv_bfloat16 h = __float2bfloat16(v);
        hi[i] = h;
        lo[i] = __float2bfloat16(v - __bfloat162float(h));
    }
}

// ---------------- 8-wide projection + cos/sin / phase update ------------------
__global__ void proj8_kernel(const float* __restrict__ X, const float* __restrict__ W8,
                             const float* __restrict__ b8, const float* __restrict__ phases,
                             float* __restrict__ out, float* __restrict__ cph,
                             float* __restrict__ sph, int mode) {
    __shared__ float hs[Dq];
    const int row = blockIdx.x;
    const int tid = threadIdx.x;
    hs[tid]       = X[(size_t)row * Dq + tid];
    hs[tid + 256] = X[(size_t)row * Dq + tid + 256];
    __syncthreads();
    const int w = tid >> 5, lane = tid & 31;
    float s = 0.f;
    #pragma unroll
    for (int kk = lane; kk < Dq; kk += 32) s += hs[kk] * W8[kk * Hq + w];
    #pragma unroll
    for (int o = 16; o; o >>= 1) s += __shfl_xor_sync(0xffffffffu, s, o);
    if (lane == 0) {
        s += b8[w];
        if (mode) {
            out[(size_t)row * Hq + w] = phases[(size_t)row * Hq + w] + 0.31415926535897932f * tanhf(s);
        } else {
            out[(size_t)row * Hq + w] = s;
            const int b = row >> 11, n = row & 2047;
            cph[(size_t)(b * Hq + w) * Nq + n] = cosf(s);
            sph[(size_t)(b * Hq + w) * Nq + n] = sinf(s);
        }
    }
}

// ---------------- residual add + LayerNorm (+ optional split out) -------------
__global__ void addln_kernel(const float* __restrict__ X, const float* __restrict__ Y,
                             const float* __restrict__ g, const float* __restrict__ be,
                             float* __restrict__ out,
                             __nv_bfloat16* __restrict__ ohi, __nv_bfloat16* __restrict__ olo) {
    __shared__ float red[256];
    const size_t row = blockIdx.x;
    const int tid = threadIdx.x;
    float a0 = X[row * Dq + tid]       + Y[row * Dq + tid];
    float a1 = X[row * Dq + tid + 256] + Y[row * Dq + tid + 256];
    red[tid] = a0 + a1; __syncthreads();
    #pragma unroll
    for (int o = 128; o; o >>= 1) { if (tid < o) red[tid] += red[tid + o]; __syncthreads(); }
    const float mu = red[0] * (1.f / Dq); __syncthreads();
    const float d0 = a0 - mu, d1 = a1 - mu;
    red[tid] = d0 * d0 + d1 * d1; __syncthreads();
    #pragma unroll
    for (int o = 128; o; o >>= 1) { if (tid < o) red[tid] += red[tid + o]; __syncthreads(); }
    const float rstd = rsqrtf(red[0] * (1.f / Dq) + 1e-5f);
    const float r0 = d0 * rstd * g[tid]       + be[tid];
    const float r1 = d1 * rstd * g[tid + 256] + be[tid + 256];
    out[row * Dq + tid]       = r0;
    out[row * Dq + tid + 256] = r1;
    if (ohi) {
        const __nv_bfloat16 h0 = __float2bfloat16(r0);
        const __nv_bfloat16 h1b = __float2bfloat16(r1);
        ohi[row * Dq + tid]       = h0;
        ohi[row * Dq + tid + 256] = h1b;
        olo[row * Dq + tid]       = __float2bfloat16(r0 - __bfloat162float(h0));
        olo[row * Dq + tid + 256] = __float2bfloat16(r1 - __bfloat162float(h1b));
    }
}

// ---------------- delta = mean_row ||h2 - h|| ---------------------------------
__global__ void rownorm_kernel(const float* __restrict__ h2, const float* __restrict__ h,
                               float* __restrict__ rn) {
    __shared__ float red[256];
    const size_t row = blockIdx.x;
    const int tid = threadIdx.x;
    float d0 = h2[row * Dq + tid]       - h[row * Dq + tid];
    float d1 = h2[row * Dq + tid + 256] - h[row * Dq + tid + 256];
    red[tid] = d0 * d0 + d1 * d1; __syncthreads();
    #pragma unroll
    for (int o = 128; o; o >>= 1) { if (tid < o) red[tid] += red[tid + o]; __syncthreads(); }
    if (tid == 0) rn[row] = sqrtf(red[0]);
}

__global__ void delta_kernel(const float* __restrict__ rn, float* __restrict__ out) {
    __shared__ float red[256];
    const int tid = threadIdx.x;
    float s = 0.f;
    for (int i = tid; i < ROWS; i += 256) s += rn[i];
    red[tid] = s; __syncthreads();
    #pragma unroll
    for (int o = 128; o; o >>= 1) { if (tid < o) red[tid] += red[tid + o]; __syncthreads(); }
    if (tid == 0) out[0] = red[0] * (1.f / ROWS);
}

// ---------------- launch ------------------------------------------------------
extern "C" void kernel_launch(void* const* d_in, const int* in_sizes, int n_in,
                              void* d_out, int out_size) {
    const float* h      = (const float*)d_in[0];
    const float* phases = (const float*)d_in[1];
    const unsigned char* mask = (const unsigned char*)d_in[2];
    const float* Wq  = (const float*)d_in[3];
    const float* Wk  = (const float*)d_in[4];
    const float* Wp  = (const float*)d_in[5];
    const float* bp  = (const float*)d_in[6];
    const float* Wv  = (const float*)d_in[7];
    const float* Wo  = (const float*)d_in[8];
    const float* W1  = (const float*)d_in[9];
    const float* b1  = (const float*)d_in[10];
    const float* W2  = (const float*)d_in[11];
    const float* b2  = (const float*)d_in[12];
    const float* g1  = (const float*)d_in[13];
    const float* be1 = (const float*)d_in[14];
    const float* g2  = (const float*)d_in[15];
    const float* be2 = (const float*)d_in[16];
    const float* Wph = (const float*)d_in[17];
    const float* bph = (const float*)d_in[18];

    float* out_h2     = (float*)d_out;
    float* out_phases = out_h2 + (size_t)ROWS * Dq;
    float* out_delta  = out_phases + (size_t)ROWS * Hq;

    float *ph, *cphp, *sphp, *msgO, *h1, *ffn2, *rn;
    __nv_bfloat16 *Qb, *Kb, *Vb, *hhi, *hlo, *h1hi, *h1lo, *mhi, *f1hi, *f1lo;
    __nv_bfloat16 *WqTh, *WqTl, *WkTh, *WkTl, *WvTh, *WvTl, *WoTh, *WoTl, *W1Th, *W1Tl, *W2Th, *W2Tl;
    cudaGetSymbolAddress((void**)&ph, g_ph);
    cudaGetSymbolAddress((void**)&cphp, g_cph); cudaGetSymbolAddress((void**)&sphp, g_sph);
    cudaGetSymbolAddress((void**)&msgO, g_msgO);
    cudaGetSymbolAddress((void**)&h1, g_h1);    cudaGetSymbolAddress((void**)&ffn2, g_ffn2);
    cudaGetSymbolAddress((void**)&rn, g_rn);
    cudaGetSymbolAddress((void**)&Qb, g_Qb);    cudaGetSymbolAddress((void**)&Kb, g_Kb);
    cudaGetSymbolAddress((void**)&Vb, g_Vb);
    cudaGetSymbolAddress((void**)&hhi, g_h_hi); cudaGetSymbolAddress((void**)&hlo, g_h_lo);
    cudaGetSymbolAddress((void**)&h1hi, g_h1_hi); cudaGetSymbolAddress((void**)&h1lo, g_h1_lo);
    cudaGetSymbolAddress((void**)&mhi, g_msg_hi);
    cudaGetSymbolAddress((void**)&f1hi, g_ffn1_hi); cudaGetSymbolAddress((void**)&f1lo, g_ffn1_lo);
    cudaGetSymbolAddress((void**)&WqTh, g_WqT_hi); cudaGetSymbolAddress((void**)&WqTl, g_WqT_lo);
    cudaGetSymbolAddress((void**)&WkTh, g_WkT_hi); cudaGetSymbolAddress((void**)&WkTl, g_WkT_lo);
    cudaGetSymbolAddress((void**)&WvTh, g_WvT_hi); cudaGetSymbolAddress((void**)&WvTl, g_WvT_lo);
    cudaGetSymbolAddress((void**)&WoTh, g_WoT_hi); cudaGetSymbolAddress((void**)&WoTl, g_WoT_lo);
    cudaGetSymbolAddress((void**)&W1Th, g_W1T_hi); cudaGetSymbolAddress((void**)&W1Tl, g_W1T_lo);
    cudaGetSymbolAddress((void**)&W2Th, g_W2T_hi); cudaGetSymbolAddress((void**)&W2Tl, g_W2T_lo);

    cudaFuncSetAttribute(flash_kernel, cudaFuncAttributeMaxDynamicSharedMemorySize, FLASH_SMEM);
    cudaFuncSetAttribute(tgemm_kernel<3>, cudaFuncAttributeMaxDynamicSharedMemorySize, 2 * 4 * TILE_B);

    wtrans_all_kernel<<<3072, dim3(32, 8)>>>(Wq, Wk, Wv, Wo, W1, W2,
        WqTh, WqTl, WkTh, WkTl, WvTh, WvTl, WoTh, WoTl, W1Th, W1Tl, W2Th, W2Tl);
    fsplit_kernel<<<(ROWS * Dq + 255) / 256, 256>>>(h, hhi, hlo, ROWS * Dq);

    const dim3 gDD(Dq / 128, ROWS / 128);
    const dim3 gDF(Fq / 128, ROWS / 128);
    const int sm1 = 2 * 2 * TILE_B;           // 40960
    const int sm3 = 2 * 4 * TILE_B;           // 81920

    // projections -> bf16 (1-term)
    tgemm_kernel<1><<<gDD, 256, sm1>>>(hhi, nullptr, WqTh, nullptr, nullptr, nullptr, Qb, nullptr, Dq, Dq, 8);
    tgemm_kernel<1><<<gDD, 256, sm1>>>(hhi, nullptr, WkTh, nullptr, nullptr, nullptr, Kb, nullptr, Dq, Dq, 8);
    tgemm_kernel<1><<<gDD, 256, sm1>>>(hhi, nullptr, WvTh, nullptr, nullptr, nullptr, Vb, nullptr, Dq, Dq, 8);
    proj8_kernel<<<ROWS, 256>>>(h, Wp, bp, nullptr, ph, cphp, sphp, 0);

    // fused flash attention
    flash_kernel<<<dim3(Nq / 128, BHq), 256, FLASH_SMEM>>>(Qb, Kb, Vb, cphp, sphp, mask, mhi);

    tgemm_kernel<1><<<gDD, 256, sm1>>>(mhi, nullptr, WoTh, nullptr, nullptr, msgO, nullptr, nullptr, Dq, Dq, 0);
    addln_kernel<<<ROWS, 256>>>(h, msgO, g1, be1, h1, h1hi, h1lo);

    // FFN (3-term, merged loading)
    tgemm_kernel<3><<<gDF, 256, sm3>>>(h1hi, h1lo, W1Th, W1Tl, b1, nullptr, f1hi, f1lo, Dq, Fq, 7);
    tgemm_kernel<3><<<gDD, 256, sm3>>>(f1hi, f1lo, W2Th, W2Tl, b2, ffn2, nullptr, nullptr, Fq, Dq, 1);
    addln_kernel<<<ROWS, 256>>>(h1, ffn2, g2, be2, out_h2, nullptr, nullptr);

    // phase update + delta
    proj8_kernel<<<ROWS, 256>>>(out_h2, Wph, bph, phases, out_phases, nullptr, nullptr, 1);
    rownorm_kernel<<<ROWS, 256>>>(out_h2, h, rn);
    delta_kernel<<<1, 256>>>(rn, out_delta);
}

// round 6
// speedup vs baseline: 5.6323x; 1.0809x over previous
#include <cuda_runtime.h>
#include <cuda_bf16.h>
#include <math.h>
#include <stdint.h>

#define Bq 2
#define Nq 2048
#define Dq 512
#define Hq 8
#define Fq 2048
#define DHq 64
#define ROWS (Bq*Nq)            // 4096
#define BHq (Bq*Hq)             // 16
#define QKVS (3*Dq)             // 1536

// ---------------- scratch (static device globals) ---------------------------
__device__ float g_ph[ROWS*Hq];
__device__ float g_cph[BHq*Nq];
__device__ float g_sph[BHq*Nq];
__device__ float g_msgO[ROWS*Dq];
__device__ float g_h1[ROWS*Dq];
__device__ float g_ffn2[ROWS*Dq];
__device__ float g_rn[ROWS];

__device__ __nv_bfloat16 g_QKVb[(size_t)ROWS*QKVS];
__device__ __nv_bfloat16 g_h_hi[ROWS*Dq];
__device__ __nv_bfloat16 g_h1_hi[ROWS*Dq],  g_h1_lo[ROWS*Dq];
__device__ __nv_bfloat16 g_msg_hi[ROWS*Dq];
__device__ __nv_bfloat16 g_ffn1_hi[(size_t)ROWS*Fq], g_ffn1_lo[(size_t)ROWS*Fq];
__device__ __nv_bfloat16 g_WqkvT_hi[3*Dq*Dq];
__device__ __nv_bfloat16 g_WoT_hi[Dq*Dq];
__device__ __nv_bfloat16 g_W1T_hi[(size_t)Fq*Dq], g_W1T_lo[(size_t)Fq*Dq];
__device__ __nv_bfloat16 g_W2T_hi[(size_t)Dq*Fq], g_W2T_lo[(size_t)Dq*Fq];

// ---------------- PTX helpers -----------------------------------------------
__device__ __forceinline__ uint32_t smem_u32(const void* p) {
    return (uint32_t)__cvta_generic_to_shared(p);
}
__device__ __forceinline__ void cp16(uint32_t s, const void* g) {
    asm volatile("cp.async.cg.shared.global [%0], [%1], 16;" :: "r"(s), "l"(g));
}
__device__ __forceinline__ void cp_commit() { asm volatile("cp.async.commit_group;" ::: "memory"); }
__device__ __forceinline__ void cp_wait1()  { asm volatile("cp.async.wait_group 1;" ::: "memory"); }

__device__ __forceinline__ void ldm_x4(uint32_t* r, uint32_t addr) {
    asm volatile("ldmatrix.sync.aligned.m8n8.x4.shared.b16 {%0,%1,%2,%3}, [%4];"
                 : "=r"(r[0]), "=r"(r[1]), "=r"(r[2]), "=r"(r[3]) : "r"(addr));
}
__device__ __forceinline__ void ldm_x4_t(uint32_t* r, uint32_t addr) {
    asm volatile("ldmatrix.sync.aligned.m8n8.x4.trans.shared.b16 {%0,%1,%2,%3}, [%4];"
                 : "=r"(r[0]), "=r"(r[1]), "=r"(r[2]), "=r"(r[3]) : "r"(addr));
}
__device__ __forceinline__ void mma16816(float* c, const uint32_t* a, const uint32_t* b) {
    asm volatile("mma.sync.aligned.m16n8k16.row.col.f32.bf16.bf16.f32 "
                 "{%0,%1,%2,%3}, {%4,%5,%6,%7}, {%8,%9}, {%0,%1,%2,%3};"
                 : "+f"(c[0]), "+f"(c[1]), "+f"(c[2]), "+f"(c[3])
                 : "r"(a[0]), "r"(a[1]), "r"(a[2]), "r"(a[3]), "r"(b[0]), "r"(b[1]));
}
__device__ __forceinline__ uint32_t pack2(float x, float y) {
    __nv_bfloat162 t = __float22bfloat162_rn(make_float2(x, y));
    return *(uint32_t*)&t;
}

// ---------------- HMMA bf16 GEMM: C = A(MxK) @ BT(NxK)^T ---------------------
// TERMS=1: C = Ahi@Bhi^T ; TERMS=3: + Ahi@Blo^T + Alo@Bhi^T
// epi bit0: +bias ; bit1: GELU ; bit2: bf16 hi/lo out ; bit3: plain bf16 out
#define TSTR 40
#define TILE_B (128 * TSTR * 2)         // 10240 bytes per tile
template<int TERMS, int STAGES>
__global__ __launch_bounds__(256) void tgemm_kernel(
    const __nv_bfloat16* __restrict__ A_hi, const __nv_bfloat16* __restrict__ A_lo,
    const __nv_bfloat16* __restrict__ B_hi, const __nv_bfloat16* __restrict__ B_lo,
    const float* __restrict__ bias,
    float* __restrict__ Cf, __nv_bfloat16* __restrict__ C_hi, __nv_bfloat16* __restrict__ C_lo,
    int K, int Nc, int epi)
{
    extern __shared__ __align__(128) unsigned char dsm[];
    const int NT = (TERMS == 3) ? 4 : 2;
    const uint32_t stg = NT * TILE_B;
    const uint32_t sb = smem_u32(dsm);
    const int tid = threadIdx.x;
    const int warp = tid >> 5, lane = tid & 31;
    const int wm = warp >> 1, wn = warp & 1;
    const int bm = blockIdx.y * 128, bn = blockIdx.x * 128;

    const int NCH = K >> 5;
    const int lrow = tid >> 2, lch = (tid & 3) << 3;

    float acc[2][8][4];
    #pragma unroll
    for (int i = 0; i < 2; i++)
        #pragma unroll
        for (int j = 0; j < 8; j++)
            #pragma unroll
            for (int q = 0; q < 4; q++) acc[i][j][q] = 0.f;

    auto issue = [&](int c) {
        if (c < NCH) {
            const int kc = c << 5;
            const uint32_t base = sb + (uint32_t)(c % STAGES) * stg;
            #pragma unroll
            for (int i = 0; i < 2; i++) {
                const int row = lrow + i * 64;
                const uint32_t so = (uint32_t)(row * TSTR + lch) * 2;
                cp16(base + so,          A_hi + (size_t)(bm + row) * K + kc + lch);
                cp16(base + TILE_B + so, B_hi + (size_t)(bn + row) * K + kc + lch);
                if (TERMS == 3) {
                    cp16(base + 2 * TILE_B + so, A_lo + (size_t)(bm + row) * K + kc + lch);
                    cp16(base + 3 * TILE_B + so, B_lo + (size_t)(bn + row) * K + kc + lch);
                }
            }
        }
        cp_commit();
    };

    #pragma unroll
    for (int p = 0; p < STAGES - 1; p++) issue(p);

    for (int c = 0; c < NCH; c++) {
        asm volatile("cp.async.wait_group %0;" :: "n"(STAGES - 2));
        __syncthreads();
        issue(c + STAGES - 1);
        const uint32_t base = sb + (uint32_t)(c % STAGES) * stg;
        #pragma unroll
        for (int ks = 0; ks < 2; ks++) {
            const uint32_t arow = (uint32_t)((wm * 32 + (lane & 15)) * TSTR
                                             + ks * 16 + ((lane >> 4) << 3)) * 2;
            const uint32_t brow = (uint32_t)((wn * 64 + ((lane >> 4) << 3) + (lane & 7)) * TSTR
                                             + ks * 16 + (((lane >> 3) & 1) << 3)) * 2;
            uint32_t aH[2][4], bH[4][4];
            #pragma unroll
            for (int mt = 0; mt < 2; mt++)
                ldm_x4(aH[mt], base + arow + (uint32_t)(mt * 16 * TSTR) * 2);
            #pragma unroll
            for (int nt4 = 0; nt4 < 4; nt4++)
                ldm_x4(bH[nt4], base + TILE_B + brow + (uint32_t)(nt4 * 16 * TSTR) * 2);
            #pragma unroll
            for (int mt = 0; mt < 2; mt++)
                #pragma unroll
                for (int nt = 0; nt < 8; nt++)
                    mma16816(acc[mt][nt], aH[mt], &bH[nt >> 1][(nt & 1) * 2]);
            if (TERMS == 3) {
                uint32_t bL[4][4];
                #pragma unroll
                for (int nt4 = 0; nt4 < 4; nt4++)
                    ldm_x4(bL[nt4], base + 3 * TILE_B + brow + (uint32_t)(nt4 * 16 * TSTR) * 2);
                #pragma unroll
                for (int mt = 0; mt < 2; mt++)
                    #pragma unroll
                    for (int nt = 0; nt < 8; nt++)
                        mma16816(acc[mt][nt], aH[mt], &bL[nt >> 1][(nt & 1) * 2]);
                uint32_t aL[2][4];
                #pragma unroll
                for (int mt = 0; mt < 2; mt++)
                    ldm_x4(aL[mt], base + 2 * TILE_B + arow + (uint32_t)(mt * 16 * TSTR) * 2);
                #pragma unroll
                for (int mt = 0; mt < 2; mt++)
                    #pragma unroll
                    for (int nt = 0; nt < 8; nt++)
                        mma16816(acc[mt][nt], aL[mt], &bH[nt >> 1][(nt & 1) * 2]);
            }
        }
        __syncthreads();
    }

    #pragma unroll
    for (int mt = 0; mt < 2; mt++) {
        const int r0 = bm + wm * 32 + mt * 16 + (lane >> 2);
        #pragma unroll
        for (int nt = 0; nt < 8; nt++) {
            const int gn = bn + wn * 64 + nt * 8 + ((lane & 3) << 1);
            #pragma unroll
            for (int half = 0; half < 2; half++) {
                const int row = r0 + half * 8;
                float v0 = acc[mt][nt][half * 2 + 0];
                float v1 = acc[mt][nt][half * 2 + 1];
                if (epi & 1) { v0 += bias[gn]; v1 += bias[gn + 1]; }
                if (epi & 2) {
                    v0 = 0.5f * v0 * (1.f + erff(v0 * 0.7071067811865475f));
                    v1 = 0.5f * v1 * (1.f + erff(v1 * 0.7071067811865475f));
                }
                const size_t idx = (size_t)row * Nc + gn;
                if (epi & 4) {
                    const __nv_bfloat16 h0 = __float2bfloat16(v0);
                    const __nv_bfloat16 h1 = __float2bfloat16(v1);
                    C_hi[idx] = h0;      C_hi[idx + 1] = h1;
                    C_lo[idx] = __float2bfloat16(v0 - __bfloat162float(h0));
                    C_lo[idx + 1] = __float2bfloat16(v1 - __bfloat162float(h1));
                } else if (epi & 8) {
                    *(__nv_bfloat162*)(C_hi + idx) =
                        __float22bfloat162_rn(make_float2(v0, v1));
                } else {
                    *(float2*)(Cf + idx) = make_float2(v0, v1);
                }
            }
        }
    }
}

// ---------------- fused flash attention (bf16 HMMA) --------------------------
#define FLASH_STAGE 38016
#define FLASH_SMEM (18432 + 2 * FLASH_STAGE)
__global__ __launch_bounds__(256) void flash_kernel(
    const __nv_bfloat16* __restrict__ QKV,
    const float* __restrict__ cph, const float* __restrict__ sph,
    const unsigned char* __restrict__ mask,
    __nv_bfloat16* __restrict__ Mhi)
{
    extern __shared__ __align__(128) unsigned char fsm[];
    const int tid = threadIdx.x, warp = tid >> 5, lane = tid & 31;
    const int bh = blockIdx.y, b = bh >> 3, hh = bh & 7;
    const int n0 = blockIdx.x * 128;
    const uint32_t sb = smem_u32(fsm);

    const __nv_bfloat16* gQ = QKV + ((size_t)b * Nq + n0) * QKVS + hh * DHq;
    #pragma unroll
    for (int i = 0; i < 4; i++) {
        const int id = tid + i * 256, row = id >> 3, ch = id & 7;
        cp16(sb + row * 144 + ch * 16, gQ + (size_t)row * QKVS + ch * 8);
    }
    cp_commit();

    auto issueKV = [&](int step, int s) {
        const uint32_t ku = sb + 18432 + s * FLASH_STAGE;
        const uint32_t vu = ku + 18432, cku = ku + 36864, sku = ku + 37376, mku = ku + 37888;
        const __nv_bfloat16* gK = QKV + ((size_t)b * Nq + step * 128) * QKVS + Dq + hh * DHq;
        const __nv_bfloat16* gV = gK + Dq;
        #pragma unroll
        for (int i = 0; i < 4; i++) {
            const int id = tid + i * 256, row = id >> 3, ch = id & 7;
            cp16(ku + row * 144 + ch * 16, gK + (size_t)row * QKVS + ch * 8);
            cp16(vu + row * 144 + ch * 16, gV + (size_t)row * QKVS + ch * 8);
        }
        if (tid < 32)      cp16(cku + tid * 16, cph + (size_t)bh * Nq + step * 128 + tid * 4);
        else if (tid < 64) cp16(sku + (tid - 32) * 16, sph + (size_t)bh * Nq + step * 128 + (tid - 32) * 4);
        else if (tid < 72) cp16(mku + (tid - 64) * 16, mask + (size_t)b * Nq + step * 128 + (tid - 64) * 16);
        cp_commit();
    };
    issueKV(0, 0);
    issueKV(1, 1);
    cp_wait1();
    __syncthreads();

    const int nw = warp * 16, r = lane >> 2;
    uint32_t qf[4][4];
    #pragma unroll
    for (int kc = 0; kc < 4; kc++)
        ldm_x4(qf[kc], sb + (uint32_t)((nw + (lane & 15)) * 144 + (kc * 16 + ((lane >> 4) << 3)) * 2));
    const float cq0 = cph[(size_t)bh * Nq + n0 + nw + r];
    const float sq0 = sph[(size_t)bh * Nq + n0 + nw + r];
    const float cq1 = cph[(size_t)bh * Nq + n0 + nw + r + 8];
    const float sq1 = sph[(size_t)bh * Nq + n0 + nw + r + 8];

    float O[8][4];
    #pragma unroll
    for (int i = 0; i < 8; i++)
        #pragma unroll
        for (int j = 0; j < 4; j++) O[i][j] = 0.f;
    float mr0 = -1e30f, mr1 = -1e30f, l0 = 0.f, l1 = 0.f;

    const int NSTEP = Nq / 128;
    for (int c = 0; c < NSTEP; c++) {
        if (c > 0) { cp_wait1(); __syncthreads(); }
        const uint32_t ku = sb + 18432 + (c & 1) * FLASH_STAGE;
        const uint32_t vu = ku + 18432;
        const float* ck = (const float*)(fsm + 18432 + (c & 1) * FLASH_STAGE + 36864);
        const float* sk = ck + 128;
        const unsigned char* mkb = (const unsigned char*)(sk + 128);

        float c_[16][4];
        #pragma unroll
        for (int g = 0; g < 16; g++)
            #pragma unroll
            for (int q = 0; q < 4; q++) c_[g][q] = 0.f;

        #pragma unroll
        for (int kc = 0; kc < 4; kc++) {
            #pragma unroll
            for (int gp = 0; gp < 8; gp++) {
                uint32_t bb[4];
                ldm_x4(bb, ku + (uint32_t)((gp * 16 + ((lane >> 4) << 3) + (lane & 7)) * 144
                                           + (kc * 16 + (((lane >> 3) & 1) << 3)) * 2));
                mma16816(c_[2 * gp],     qf[kc], bb);
                mma16816(c_[2 * gp + 1], qf[kc], bb + 2);
            }
        }

        float mx0 = -1e30f, mx1 = -1e30f;
        #pragma unroll
        for (int g = 0; g < 16; g++) {
            const int cg = g * 8 + ((lane & 3) << 1);
            const float2 cm = *(const float2*)(ck + cg);
            const float2 sv = *(const float2*)(sk + cg);
            float s0 = c_[g][0] * (0.0625f + 0.0625f * (cq0 * cm.x + sq0 * sv.x));
            float s1 = c_[g][1] * (0.0625f + 0.0625f * (cq0 * cm.y + sq0 * sv.y));
            float s2 = c_[g][2] * (0.0625f + 0.0625f * (cq1 * cm.x + sq1 * sv.x));
            float s3 = c_[g][3] * (0.0625f + 0.0625f * (cq1 * cm.y + sq1 * sv.y));
            if (mkb[cg])     { s0 = -1e30f; s2 = -1e30f; }
            if (mkb[cg + 1]) { s1 = -1e30f; s3 = -1e30f; }
            c_[g][0] = s0; c_[g][1] = s1; c_[g][2] = s2; c_[g][3] = s3;
            mx0 = fmaxf(mx0, fmaxf(s0, s1));
            mx1 = fmaxf(mx1, fmaxf(s2, s3));
        }
        mx0 = fmaxf(mx0, __shfl_xor_sync(~0u, mx0, 1));
        mx0 = fmaxf(mx0, __shfl_xor_sync(~0u, mx0, 2));
        mx1 = fmaxf(mx1, __shfl_xor_sync(~0u, mx1, 1));
        mx1 = fmaxf(mx1, __shfl_xor_sync(~0u, mx1, 2));
        const float mn0 = fmaxf(mr0, mx0), mn1 = fmaxf(mr1, mx1);
        const float sc0 = __expf(mr0 - mn0), sc1 = __expf(mr1 - mn1);
        mr0 = mn0; mr1 = mn1;
        l0 *= sc0; l1 *= sc1;
        #pragma unroll
        for (int dg = 0; dg < 8; dg++) {
            O[dg][0] *= sc0; O[dg][1] *= sc0; O[dg][2] *= sc1; O[dg][3] *= sc1;
        }
        #pragma unroll
        for (int g = 0; g < 16; g++) {
            const float p0 = __expf(c_[g][0] - mr0), p1 = __expf(c_[g][1] - mr0);
            const float p2 = __expf(c_[g][2] - mr1), p3 = __expf(c_[g][3] - mr1);
            c_[g][0] = p0; c_[g][1] = p1; c_[g][2] = p2; c_[g][3] = p3;
            l0 += p0 + p1; l1 += p2 + p3;
        }

        #pragma unroll
        for (int kc2 = 0; kc2 < 8; kc2++) {
            uint32_t a[4];
            a[0] = pack2(c_[2 * kc2][0],     c_[2 * kc2][1]);
            a[1] = pack2(c_[2 * kc2][2],     c_[2 * kc2][3]);
            a[2] = pack2(c_[2 * kc2 + 1][0], c_[2 * kc2 + 1][1]);
            a[3] = pack2(c_[2 * kc2 + 1][2], c_[2 * kc2 + 1][3]);
            #pragma unroll
            for (int dgp = 0; dgp < 4; dgp++) {
                uint32_t bb[4];
                ldm_x4_t(bb, vu + (uint32_t)((kc2 * 16 + (lane & 15)) * 144
                                             + (dgp * 16 + ((lane >> 4) << 3)) * 2));
                mma16816(O[2 * dgp],     a, bb);
                mma16816(O[2 * dgp + 1], a, bb + 2);
            }
        }
        __syncthreads();
        if (c + 2 < NSTEP) issueKV(c + 2, c & 1);
    }

    l0 += __shfl_xor_sync(~0u, l0, 1); l0 += __shfl_xor_sync(~0u, l0, 2);
    l1 += __shfl_xor_sync(~0u, l1, 1); l1 += __shfl_xor_sync(~0u, l1, 2);
    const float i0 = 1.f / l0, i1 = 1.f / l1;
    const size_t row0 = (size_t)(b * Nq + n0 + nw + r) * Dq + hh * DHq;
    const size_t row1 = row0 + 8 * Dq;
    #pragma unroll
    for (int dg = 0; dg < 8; dg++) {
        const int d = dg * 8 + ((lane & 3) << 1);
        *(__nv_bfloat162*)(Mhi + row0 + d) =
            __float22bfloat162_rn(make_float2(O[dg][0] * i0, O[dg][1] * i0));
        *(__nv_bfloat162*)(Mhi + row1 + d) =
            __float22bfloat162_rn(make_float2(O[dg][2] * i1, O[dg][3] * i1));
    }
}

// ---------------- fused weight transpose+split ------------------------------
__device__ __forceinline__ void wtile(const float* __restrict__ W, __nv_bfloat16* __restrict__ Th,
                                      __nv_bfloat16* __restrict__ Tl, int K, int Nc,
                                      int k0, int n0, int tx, int ty, float t[32][33]) {
    #pragma unroll
    for (int i = ty; i < 32; i += 8) t[i][tx] = W[(size_t)(k0 + i) * Nc + n0 + tx];
    __syncthreads();
    #pragma unroll
    for (int i = ty; i < 32; i += 8) {
        const float v = t[tx][i];
        const __nv_bfloat16 hi = __float2bfloat16(v);
        Th[(size_t)(n0 + i) * K + k0 + tx] = hi;
        if (Tl) Tl[(size_t)(n0 + i) * K + k0 + tx] = __float2bfloat16(v - __bfloat162float(hi));
    }
}

__global__ void wtrans_all_kernel(
    const float* Wq, const float* Wk, const float* Wv, const float* Wo,
    const float* W1, const float* W2,
    __nv_bfloat16* qkvh, __nv_bfloat16* oh,
    __nv_bfloat16* w1h, __nv_bfloat16* w1l, __nv_bfloat16* w2h, __nv_bfloat16* w2l)
{
    __shared__ float t[32][33];
    const int tx = threadIdx.x, ty = threadIdx.y;
    int id = blockIdx.x;
    if (id < 1024) {
        const int w = id >> 8, tl = id & 255;
        const int n0 = (tl & 15) * 32, k0 = (tl >> 4) * 32;
        const float* W = (w == 0) ? Wq : (w == 1) ? Wk : (w == 2) ? Wv : Wo;
        __nv_bfloat16* Th = (w < 3) ? (qkvh + (size_t)w * Dq * Dq) : oh;
        wtile(W, Th, nullptr, Dq, Dq, k0, n0, tx, ty, t);
    } else if (id < 2048) {
        const int tl = id - 1024;
        const int n0 = (tl & 63) * 32, k0 = (tl >> 6) * 32;
        wtile(W1, w1h, w1l, Dq, Fq, k0, n0, tx, ty, t);
    } else {
        const int tl = id - 2048;
        const int n0 = (tl & 15) * 32, k0 = (tl >> 4) * 32;
        wtile(W2, w2h, w2l, Fq, Dq, k0, n0, tx, ty, t);
    }
}

__global__ void fsplit_kernel(const float* __restrict__ X, __nv_bfloat16* __restrict__ hi, int n) {
    const int i = blockIdx.x * 256 + threadIdx.x;
    if (i < n) hi[i] = __float2bfloat16(X[i]);
}

// ---------------- 8-wide projection + cos/sin / phase update -----------------
// grid ROWS/8, block 256 (warp per row)
__global__ __launch_bounds__(256) void proj8_kernel(
    const float* __restrict__ X, const float* __restrict__ W8,
    const float* __restrict__ b8, const float* __restrict__ phases,
    float* __restrict__ out, float* __restrict__ cph, float* __restrict__ sph, int mode)
{
    __shared__ float xs[8][Dq];
    __shared__ float w8t[8][Dq];
    __shared__ float b8s[8];
    const int tid = threadIdx.x;
    const int r0 = blockIdx.x * 8;
    for (int i = tid; i < 8 * (Dq / 4); i += 256) {
        const int row = i >> 7, c4 = i & 127;
        ((float4*)xs[row])[c4] = ((const float4*)(X + (size_t)(r0 + row) * Dq))[c4];
    }
    for (int i = tid; i < Dq * 8; i += 256) w8t[i & 7][i >> 3] = W8[i];
    if (tid < 8) b8s[tid] = b8[tid];
    __syncthreads();
    const int warp = tid >> 5, lane = tid & 31;
    const int row = r0 + warp;
    float acc[8] = {0.f, 0.f, 0.f, 0.f, 0.f, 0.f, 0.f, 0.f};
    #pragma unroll
    for (int i = 0; i < 16; i++) {
        const int kk = lane + i * 32;
        const float xv = xs[warp][kk];
        #pragma unroll
        for (int w = 0; w < 8; w++) acc[w] += xv * w8t[w][kk];
    }
    float res = 0.f;
    #pragma unroll
    for (int w = 0; w < 8; w++) {
        #pragma unroll
        for (int o = 16; o; o >>= 1) acc[w] += __shfl_xor_sync(~0u, acc[w], o);
        if (lane == w) res = acc[w];
    }
    if (lane < 8) {
        float s = res + b8s[lane];
        if (mode) {
            out[(size_t)row * Hq + lane] = phases[(size_t)row * Hq + lane]
                                           + 0.31415926535897932f * tanhf(s);
        } else {
            out[(size_t)row * Hq + lane] = s;
            const int b = row >> 11, n = row & 2047;
            cph[(size_t)(b * Hq + lane) * Nq + n] = cosf(s);
            sph[(size_t)(b * Hq + lane) * Nq + n] = sinf(s);
        }
    }
}

// ---------------- residual add + LayerNorm (warp per row) --------------------
__global__ __launch_bounds__(256) void addln_kernel(
    const float* __restrict__ X, const float* __restrict__ Y,
    const float* __restrict__ g, const float* __restrict__ be,
    float* __restrict__ out, __nv_bfloat16* __restrict__ ohi, __nv_bfloat16* __restrict__ olo)
{
    const int warp = threadIdx.x >> 5, lane = threadIdx.x & 31;
    const size_t row = blockIdx.x * 8 + warp;
    const float4* X4 = (const float4*)(X + row * Dq);
    const float4* Y4 = (const float4*)(Y + row * Dq);
    float a[16];
    float s = 0.f;
    #pragma unroll
    for (int i = 0; i < 4; i++) {
        const float4 xv = X4[lane + i * 32];
        const float4 yv = Y4[lane + i * 32];
        a[4 * i + 0] = xv.x + yv.x; a[4 * i + 1] = xv.y + yv.y;
        a[4 * i + 2] = xv.z + yv.z; a[4 * i + 3] = xv.w + yv.w;
        s += a[4 * i] + a[4 * i + 1] + a[4 * i + 2] + a[4 * i + 3];
    }
    #pragma unroll
    for (int o = 16; o; o >>= 1) s += __shfl_xor_sync(~0u, s, o);
    const float mu = s * (1.f / Dq);
    float vs = 0.f;
    #pragma unroll
    for (int i = 0; i < 16; i++) { const float d = a[i] - mu; vs += d * d; }
    #pragma unroll
    for (int o = 16; o; o >>= 1) vs += __shfl_xor_sync(~0u, vs, o);
    const float rstd = rsqrtf(vs * (1.f / Dq) + 1e-5f);
    #pragma unroll
    for (int i = 0; i < 4; i++) {
        const int c4 = lane + i * 32;
        const float4 gv = ((const float4*)g)[c4];
        const float4 bv = ((const float4*)be)[c4];
        float4 r;
        r.x = (a[4 * i + 0] - mu) * rstd * gv.x + bv.x;
        r.y = (a[4 * i + 1] - mu) * rstd * gv.y + bv.y;
        r.z = (a[4 * i + 2] - mu) * rstd * gv.z + bv.z;
        r.w = (a[4 * i + 3] - mu) * rstd * gv.w + bv.w;
        ((float4*)(out + row * Dq))[c4] = r;
        if (ohi) {
            const __nv_bfloat16 h0 = __float2bfloat16(r.x), h1 = __float2bfloat16(r.y);
            const __nv_bfloat16 h2 = __float2bfloat16(r.z), h3 = __float2bfloat16(r.w);
            __nv_bfloat162 hi0; hi0.x = h0; hi0.y = h1;
            __nv_bfloat162 hi1; hi1.x = h2; hi1.y = h3;
            *(__nv_bfloat162*)(ohi + row * Dq + c4 * 4)     = hi0;
            *(__nv_bfloat162*)(ohi + row * Dq + c4 * 4 + 2) = hi1;
            __nv_bfloat162 lo0, lo1;
            lo0.x = __float2bfloat16(r.x - __bfloat162float(h0));
            lo0.y = __float2bfloat16(r.y - __bfloat162float(h1));
            lo1.x = __float2bfloat16(r.z - __bfloat162float(h2));
            lo1.y = __float2bfloat16(r.w - __bfloat162float(h3));
            *(__nv_bfloat162*)(olo + row * Dq + c4 * 4)     = lo0;
            *(__nv_bfloat162*)(olo + row * Dq + c4 * 4 + 2) = lo1;
        }
    }
}

// ---------------- delta = mean_row ||h2 - h|| --------------------------------
__global__ __launch_bounds__(256) void rownorm_kernel(
    const float* __restrict__ h2, const float* __restrict__ h, float* __restrict__ rn)
{
    const int warp = threadIdx.x >> 5, lane = threadIdx.x & 31;
    const size_t row = blockIdx.x * 8 + warp;
    const float4* A4 = (const float4*)(h2 + row * Dq);
    const float4* B4 = (const float4*)(h + row * Dq);
    float s = 0.f;
    #pragma unroll
    for (int i = 0; i < 4; i++) {
        const float4 av = A4[lane + i * 32];
        const float4 bv = B4[lane + i * 32];
        const float d0 = av.x - bv.x, d1 = av.y - bv.y, d2 = av.z - bv.z, d3 = av.w - bv.w;
        s += d0 * d0 + d1 * d1 + d2 * d2 + d3 * d3;
    }
    #pragma unroll
    for (int o = 16; o; o >>= 1) s += __shfl_xor_sync(~0u, s, o);
    if (lane == 0) rn[row] = sqrtf(s);
}

__global__ void delta_kernel(const float* __restrict__ rn, float* __restrict__ out) {
    __shared__ float red[256];
    const int tid = threadIdx.x;
    float s = 0.f;
    for (int i = tid; i < ROWS; i += 256) s += rn[i];
    red[tid] = s; __syncthreads();
    #pragma unroll
    for (int o = 128; o; o >>= 1) { if (tid < o) red[tid] += red[tid + o]; __syncthreads(); }
    if (tid == 0) out[0] = red[0] * (1.f / ROWS);
}

// ---------------- launch ------------------------------------------------------
extern "C" void kernel_launch(void* const* d_in, const int* in_sizes, int n_in,
                              void* d_out, int out_size) {
    const float* h      = (const float*)d_in[0];
    const float* phases = (const float*)d_in[1];
    const unsigned char* mask = (const unsigned char*)d_in[2];
    const float* Wq  = (const float*)d_in[3];
    const float* Wk  = (const float*)d_in[4];
    const float* Wp  = (const float*)d_in[5];
    const float* bp  = (const float*)d_in[6];
    const float* Wv  = (const float*)d_in[7];
    const float* Wo  = (const float*)d_in[8];
    const float* W1  = (const float*)d_in[9];
    const float* b1  = (const float*)d_in[10];
    const float* W2  = (const float*)d_in[11];
    const float* b2  = (const float*)d_in[12];
    const float* g1  = (const float*)d_in[13];
    const float* be1 = (const float*)d_in[14];
    const float* g2  = (const float*)d_in[15];
    const float* be2 = (const float*)d_in[16];
    const float* Wph = (const float*)d_in[17];
    const float* bph = (const float*)d_in[18];

    float* out_h2     = (float*)d_out;
    float* out_phases = out_h2 + (size_t)ROWS * Dq;
    float* out_delta  = out_phases + (size_t)ROWS * Hq;

    float *ph, *cphp, *sphp, *msgO, *h1, *ffn2, *rn;
    __nv_bfloat16 *QKVb, *hhi, *h1hi, *h1lo, *mhi, *f1hi, *f1lo;
    __nv_bfloat16 *WqkvTh, *WoTh, *W1Th, *W1Tl, *W2Th, *W2Tl;
    cudaGetSymbolAddress((void**)&ph, g_ph);
    cudaGetSymbolAddress((void**)&cphp, g_cph); cudaGetSymbolAddress((void**)&sphp, g_sph);
    cudaGetSymbolAddress((void**)&msgO, g_msgO);
    cudaGetSymbolAddress((void**)&h1, g_h1);    cudaGetSymbolAddress((void**)&ffn2, g_ffn2);
    cudaGetSymbolAddress((void**)&rn, g_rn);
    cudaGetSymbolAddress((void**)&QKVb, g_QKVb);
    cudaGetSymbolAddress((void**)&hhi, g_h_hi);
    cudaGetSymbolAddress((void**)&h1hi, g_h1_hi); cudaGetSymbolAddress((void**)&h1lo, g_h1_lo);
    cudaGetSymbolAddress((void**)&mhi, g_msg_hi);
    cudaGetSymbolAddress((void**)&f1hi, g_ffn1_hi); cudaGetSymbolAddress((void**)&f1lo, g_ffn1_lo);
    cudaGetSymbolAddress((void**)&WqkvTh, g_WqkvT_hi);
    cudaGetSymbolAddress((void**)&WoTh, g_WoT_hi);
    cudaGetSymbolAddress((void**)&W1Th, g_W1T_hi); cudaGetSymbolAddress((void**)&W1Tl, g_W1T_lo);
    cudaGetSymbolAddress((void**)&W2Th, g_W2T_hi); cudaGetSymbolAddress((void**)&W2Tl, g_W2T_lo);

    const int sm1 = 4 * 2 * TILE_B;           // 81920
    const int sm3 = 3 * 4 * TILE_B;           // 122880
    cudaFuncSetAttribute(flash_kernel, cudaFuncAttributeMaxDynamicSharedMemorySize, FLASH_SMEM);
    cudaFuncSetAttribute((const void*)tgemm_kernel<1, 4>, cudaFuncAttributeMaxDynamicSharedMemorySize, sm1);
    cudaFuncSetAttribute((const void*)tgemm_kernel<3, 3>, cudaFuncAttributeMaxDynamicSharedMemorySize, sm3);

    wtrans_all_kernel<<<3072, dim3(32, 8)>>>(Wq, Wk, Wv, Wo, W1, W2,
        WqkvTh, WoTh, W1Th, W1Tl, W2Th, W2Tl);
    fsplit_kernel<<<(ROWS * Dq + 255) / 256, 256>>>(h, hhi, ROWS * Dq);

    // fused QKV projection -> bf16 (1-term), Nc = 1536
    tgemm_kernel<1, 4><<<dim3(QKVS / 128, ROWS / 128), 256, sm1>>>(
        hhi, nullptr, WqkvTh, nullptr, nullptr, nullptr, QKVb, nullptr, Dq, QKVS, 8);
    proj8_kernel<<<ROWS / 8, 256>>>(h, Wp, bp, nullptr, ph, cphp, sphp, 0);

    // fused flash attention
    flash_kernel<<<dim3(Nq / 128, BHq), 256, FLASH_SMEM>>>(QKVb, cphp, sphp, mask, mhi);

    tgemm_kernel<1, 4><<<dim3(Dq / 128, ROWS / 128), 256, sm1>>>(
        mhi, nullptr, WoTh, nullptr, nullptr, msgO, nullptr, nullptr, Dq, Dq, 0);
    addln_kernel<<<ROWS / 8, 256>>>(h, msgO, g1, be1, h1, h1hi, h1lo);

    // FFN (3-term, merged loading, 3-stage)
    tgemm_kernel<3, 3><<<dim3(Fq / 128, ROWS / 128), 256, sm3>>>(
        h1hi, h1lo, W1Th, W1Tl, b1, nullptr, f1hi, f1lo, Dq, Fq, 7);
    tgemm_kernel<3, 3><<<dim3(Dq / 128, ROWS / 128), 256, sm3>>>(
        f1hi, f1lo, W2Th, W2Tl, b2, ffn2, nullptr, nullptr, Fq, Dq, 1);
    addln_kernel<<<ROWS / 8, 256>>>(h1, ffn2, g2, be2, out_h2, nullptr, nullptr);

    // phase update + delta
    proj8_kernel<<<ROWS / 8, 256>>>(out_h2, Wph, bph, phases, out_phases, nullptr, nullptr, 1);
    rownorm_kernel<<<ROWS / 8, 256>>>(out_h2, h, rn);
    delta_kernel<<<1, 256>>>(rn, out_delta);
}

// round 7
// speedup vs baseline: 8.1222x; 1.4421x over previous
#include <cuda_runtime.h>
#include <cuda_bf16.h>
#include <cuda_fp16.h>
#include <math.h>
#include <stdint.h>

#define Bq 2
#define Nq 2048
#define Dq 512
#define Hq 8
#define Fq 2048
#define DHq 64
#define ROWS (Bq*Nq)            // 4096
#define BHq (Bq*Hq)             // 16
#define QKVS (3*Dq)             // 1536

// ---------------- scratch (static device globals) ---------------------------
__device__ float g_ph[ROWS*Hq];
__device__ float g_cph[BHq*Nq];
__device__ float g_sph[BHq*Nq];
__device__ float g_msgO[ROWS*Dq];
__device__ float g_h1[ROWS*Dq];
__device__ float g_ffn2[ROWS*Dq];
__device__ float g_rn[ROWS];

__device__ __nv_bfloat16 g_QKVb[(size_t)ROWS*QKVS];
__device__ __nv_bfloat16 g_h_hi[ROWS*Dq];
__device__ __nv_bfloat16 g_msg_hi[ROWS*Dq];
__device__ __half        g_h1h[ROWS*Dq];
__device__ __half        g_ffn1h[(size_t)ROWS*Fq];
__device__ __nv_bfloat16 g_WqkvT[3*Dq*Dq];
__device__ __nv_bfloat16 g_WoT[Dq*Dq];
__device__ __half        g_W1T[(size_t)Fq*Dq];
__device__ __half        g_W2T[(size_t)Dq*Fq];

// ---------------- PTX helpers -----------------------------------------------
__device__ __forceinline__ uint32_t smem_u32(const void* p) {
    return (uint32_t)__cvta_generic_to_shared(p);
}
__device__ __forceinline__ void cp16(uint32_t s, const void* g) {
    asm volatile("cp.async.cg.shared.global [%0], [%1], 16;" :: "r"(s), "l"(g));
}
__device__ __forceinline__ void cp_commit() { asm volatile("cp.async.commit_group;" ::: "memory"); }
__device__ __forceinline__ void cp_wait1()  { asm volatile("cp.async.wait_group 1;" ::: "memory"); }

__device__ __forceinline__ void ldm_x4(uint32_t* r, uint32_t addr) {
    asm volatile("ldmatrix.sync.aligned.m8n8.x4.shared.b16 {%0,%1,%2,%3}, [%4];"
                 : "=r"(r[0]), "=r"(r[1]), "=r"(r[2]), "=r"(r[3]) : "r"(addr));
}
__device__ __forceinline__ void ldm_x4_t(uint32_t* r, uint32_t addr) {
    asm volatile("ldmatrix.sync.aligned.m8n8.x4.trans.shared.b16 {%0,%1,%2,%3}, [%4];"
                 : "=r"(r[0]), "=r"(r[1]), "=r"(r[2]), "=r"(r[3]) : "r"(addr));
}
template<bool FP16>
__device__ __forceinline__ void mma16816(float* c, const uint32_t* a, const uint32_t* b) {
    if (FP16)
        asm volatile("mma.sync.aligned.m16n8k16.row.col.f32.f16.f16.f32 "
                     "{%0,%1,%2,%3}, {%4,%5,%6,%7}, {%8,%9}, {%0,%1,%2,%3};"
                     : "+f"(c[0]), "+f"(c[1]), "+f"(c[2]), "+f"(c[3])
                     : "r"(a[0]), "r"(a[1]), "r"(a[2]), "r"(a[3]), "r"(b[0]), "r"(b[1]));
    else
        asm volatile("mma.sync.aligned.m16n8k16.row.col.f32.bf16.bf16.f32 "
                     "{%0,%1,%2,%3}, {%4,%5,%6,%7}, {%8,%9}, {%0,%1,%2,%3};"
                     : "+f"(c[0]), "+f"(c[1]), "+f"(c[2]), "+f"(c[3])
                     : "r"(a[0]), "r"(a[1]), "r"(a[2]), "r"(a[3]), "r"(b[0]), "r"(b[1]));
}
__device__ __forceinline__ uint32_t pack2(float x, float y) {
    __nv_bfloat162 t = __float22bfloat162_rn(make_float2(x, y));
    return *(uint32_t*)&t;
}

// ---------------- HMMA 16-bit GEMM: C = A(MxK) @ BT(NxK)^T -------------------
// epi bit0: +bias ; bit1: GELU ; bit3: 16-bit out (fp16 if FP16 else bf16)
#define TSTR 40
#define TILE_B (128 * TSTR * 2)         // 10240 bytes per tile
template<int STAGES, bool FP16>
__global__ __launch_bounds__(256) void tgemm_kernel(
    const uint16_t* __restrict__ A, const uint16_t* __restrict__ B,
    const float* __restrict__ bias,
    float* __restrict__ Cf, uint16_t* __restrict__ C16,
    int K, int Nc, int epi)
{
    extern __shared__ __align__(128) unsigned char dsm[];
    const uint32_t stg = 2 * TILE_B;
    const uint32_t sb = smem_u32(dsm);
    const int tid = threadIdx.x;
    const int warp = tid >> 5, lane = tid & 31;
    const int wm = warp >> 1, wn = warp & 1;
    const int bm = blockIdx.y * 128, bn = blockIdx.x * 128;

    const int NCH = K >> 5;
    const int lrow = tid >> 2, lch = (tid & 3) << 3;

    float acc[2][8][4];
    #pragma unroll
    for (int i = 0; i < 2; i++)
        #pragma unroll
        for (int j = 0; j < 8; j++)
            #pragma unroll
            for (int q = 0; q < 4; q++) acc[i][j][q] = 0.f;

    auto issue = [&](int c) {
        if (c < NCH) {
            const int kc = c << 5;
            const uint32_t base = sb + (uint32_t)(c % STAGES) * stg;
            #pragma unroll
            for (int i = 0; i < 2; i++) {
                const int row = lrow + i * 64;
                const uint32_t so = (uint32_t)(row * TSTR + lch) * 2;
                cp16(base + so,          A + (size_t)(bm + row) * K + kc + lch);
                cp16(base + TILE_B + so, B + (size_t)(bn + row) * K + kc + lch);
            }
        }
        cp_commit();
    };

    #pragma unroll
    for (int p = 0; p < STAGES - 1; p++) issue(p);

    for (int c = 0; c < NCH; c++) {
        asm volatile("cp.async.wait_group %0;" :: "n"(STAGES - 2));
        __syncthreads();
        issue(c + STAGES - 1);
        const uint32_t base = sb + (uint32_t)(c % STAGES) * stg;
        #pragma unroll
        for (int ks = 0; ks < 2; ks++) {
            const uint32_t arow = (uint32_t)((wm * 32 + (lane & 15)) * TSTR
                                             + ks * 16 + ((lane >> 4) << 3)) * 2;
            const uint32_t brow = (uint32_t)((wn * 64 + ((lane >> 4) << 3) + (lane & 7)) * TSTR
                                             + ks * 16 + (((lane >> 3) & 1) << 3)) * 2;
            uint32_t aH[2][4], bH[4][4];
            #pragma unroll
            for (int mt = 0; mt < 2; mt++)
                ldm_x4(aH[mt], base + arow + (uint32_t)(mt * 16 * TSTR) * 2);
            #pragma unroll
            for (int nt4 = 0; nt4 < 4; nt4++)
                ldm_x4(bH[nt4], base + TILE_B + brow + (uint32_t)(nt4 * 16 * TSTR) * 2);
            #pragma unroll
            for (int mt = 0; mt < 2; mt++)
                #pragma unroll
                for (int nt = 0; nt < 8; nt++)
                    mma16816<FP16>(acc[mt][nt], aH[mt], &bH[nt >> 1][(nt & 1) * 2]);
        }
        __syncthreads();
    }

    #pragma unroll
    for (int mt = 0; mt < 2; mt++) {
        const int r0 = bm + wm * 32 + mt * 16 + (lane >> 2);
        #pragma unroll
        for (int nt = 0; nt < 8; nt++) {
            const int gn = bn + wn * 64 + nt * 8 + ((lane & 3) << 1);
            #pragma unroll
            for (int half = 0; half < 2; half++) {
                const int row = r0 + half * 8;
                float v0 = acc[mt][nt][half * 2 + 0];
                float v1 = acc[mt][nt][half * 2 + 1];
                if (epi & 1) { v0 += bias[gn]; v1 += bias[gn + 1]; }
                if (epi & 2) {
                    v0 = 0.5f * v0 * (1.f + erff(v0 * 0.7071067811865475f));
                    v1 = 0.5f * v1 * (1.f + erff(v1 * 0.7071067811865475f));
                }
                const size_t idx = (size_t)row * Nc + gn;
                if (epi & 8) {
                    if (FP16) {
                        __half2 t = __floats2half2_rn(v0, v1);
                        *(__half2*)((__half*)C16 + idx) = t;
                    } else {
                        *(__nv_bfloat162*)((__nv_bfloat16*)C16 + idx) =
                            __float22bfloat162_rn(make_float2(v0, v1));
                    }
                } else {
                    *(float2*)(Cf + idx) = make_float2(v0, v1);
                }
            }
        }
    }
}

// ---------------- fused flash attention (bf16 HMMA) --------------------------
#define FLASH_STAGE 38016
#define FLASH_SMEM (18432 + 2 * FLASH_STAGE)
__global__ __launch_bounds__(256) void flash_kernel(
    const __nv_bfloat16* __restrict__ QKV,
    const float* __restrict__ cph, const float* __restrict__ sph,
    const unsigned char* __restrict__ mask,
    __nv_bfloat16* __restrict__ Mhi)
{
    extern __shared__ __align__(128) unsigned char fsm[];
    const int tid = threadIdx.x, warp = tid >> 5, lane = tid & 31;
    const int bh = blockIdx.y, b = bh >> 3, hh = bh & 7;
    const int n0 = blockIdx.x * 128;
    const uint32_t sb = smem_u32(fsm);

    const __nv_bfloat16* gQ = QKV + ((size_t)b * Nq + n0) * QKVS + hh * DHq;
    #pragma unroll
    for (int i = 0; i < 4; i++) {
        const int id = tid + i * 256, row = id >> 3, ch = id & 7;
        cp16(sb + row * 144 + ch * 16, gQ + (size_t)row * QKVS + ch * 8);
    }
    cp_commit();

    auto issueKV = [&](int step, int s) {
        const uint32_t ku = sb + 18432 + s * FLASH_STAGE;
        const uint32_t vu = ku + 18432, cku = ku + 36864, sku = ku + 37376, mku = ku + 37888;
        const __nv_bfloat16* gK = QKV + ((size_t)b * Nq + step * 128) * QKVS + Dq + hh * DHq;
        const __nv_bfloat16* gV = gK + Dq;
        #pragma unroll
        for (int i = 0; i < 4; i++) {
            const int id = tid + i * 256, row = id >> 3, ch = id & 7;
            cp16(ku + row * 144 + ch * 16, gK + (size_t)row * QKVS + ch * 8);
            cp16(vu + row * 144 + ch * 16, gV + (size_t)row * QKVS + ch * 8);
        }
        if (tid < 32)      cp16(cku + tid * 16, cph + (size_t)bh * Nq + step * 128 + tid * 4);
        else if (tid < 64) cp16(sku + (tid - 32) * 16, sph + (size_t)bh * Nq + step * 128 + (tid - 32) * 4);
        else if (tid < 72) cp16(mku + (tid - 64) * 16, mask + (size_t)b * Nq + step * 128 + (tid - 64) * 16);
        cp_commit();
    };
    issueKV(0, 0);
    issueKV(1, 1);
    cp_wait1();
    __syncthreads();

    const int nw = warp * 16, r = lane >> 2;
    uint32_t qf[4][4];
    #pragma unroll
    for (int kc = 0; kc < 4; kc++)
        ldm_x4(qf[kc], sb + (uint32_t)((nw + (lane & 15)) * 144 + (kc * 16 + ((lane >> 4) << 3)) * 2));
    const float cq0 = cph[(size_t)bh * Nq + n0 + nw + r];
    const float sq0 = sph[(size_t)bh * Nq + n0 + nw + r];
    const float cq1 = cph[(size_t)bh * Nq + n0 + nw + r + 8];
    const float sq1 = sph[(size_t)bh * Nq + n0 + nw + r + 8];

    float O[8][4];
    #pragma unroll
    for (int i = 0; i < 8; i++)
        #pragma unroll
        for (int j = 0; j < 4; j++) O[i][j] = 0.f;
    float mr0 = -1e30f, mr1 = -1e30f, l0 = 0.f, l1 = 0.f;

    const int NSTEP = Nq / 128;
    for (int c = 0; c < NSTEP; c++) {
        if (c > 0) { cp_wait1(); __syncthreads(); }
        const uint32_t ku = sb + 18432 + (c & 1) * FLASH_STAGE;
        const uint32_t vu = ku + 18432;
        const float* ck = (const float*)(fsm + 18432 + (c & 1) * FLASH_STAGE + 36864);
        const float* sk = ck + 128;
        const unsigned char* mkb = (const unsigned char*)(sk + 128);

        float c_[16][4];
        #pragma unroll
        for (int g = 0; g < 16; g++)
            #pragma unroll
            for (int q = 0; q < 4; q++) c_[g][q] = 0.f;

        #pragma unroll
        for (int kc = 0; kc < 4; kc++) {
            #pragma unroll
            for (int gp = 0; gp < 8; gp++) {
                uint32_t bb[4];
                ldm_x4(bb, ku + (uint32_t)((gp * 16 + ((lane >> 4) << 3) + (lane & 7)) * 144
                                           + (kc * 16 + (((lane >> 3) & 1) << 3)) * 2));
                mma16816<false>(c_[2 * gp],     qf[kc], bb);
                mma16816<false>(c_[2 * gp + 1], qf[kc], bb + 2);
            }
        }

        float mx0 = -1e30f, mx1 = -1e30f;
        #pragma unroll
        for (int g = 0; g < 16; g++) {
            const int cg = g * 8 + ((lane & 3) << 1);
            const float2 cm = *(const float2*)(ck + cg);
            const float2 sv = *(const float2*)(sk + cg);
            float s0 = c_[g][0] * (0.0625f + 0.0625f * (cq0 * cm.x + sq0 * sv.x));
            float s1 = c_[g][1] * (0.0625f + 0.0625f * (cq0 * cm.y + sq0 * sv.y));
            float s2 = c_[g][2] * (0.0625f + 0.0625f * (cq1 * cm.x + sq1 * sv.x));
            float s3 = c_[g][3] * (0.0625f + 0.0625f * (cq1 * cm.y + sq1 * sv.y));
            if (mkb[cg])     { s0 = -1e30f; s2 = -1e30f; }
            if (mkb[cg + 1]) { s1 = -1e30f; s3 = -1e30f; }
            c_[g][0] = s0; c_[g][1] = s1; c_[g][2] = s2; c_[g][3] = s3;
            mx0 = fmaxf(mx0, fmaxf(s0, s1));
            mx1 = fmaxf(mx1, fmaxf(s2, s3));
        }
        mx0 = fmaxf(mx0, __shfl_xor_sync(~0u, mx0, 1));
        mx0 = fmaxf(mx0, __shfl_xor_sync(~0u, mx0, 2));
        mx1 = fmaxf(mx1, __shfl_xor_sync(~0u, mx1, 1));
        mx1 = fmaxf(mx1, __shfl_xor_sync(~0u, mx1, 2));
        const float mn0 = fmaxf(mr0, mx0), mn1 = fmaxf(mr1, mx1);
        const float sc0 = __expf(mr0 - mn0), sc1 = __expf(mr1 - mn1);
        mr0 = mn0; mr1 = mn1;
        l0 *= sc0; l1 *= sc1;
        #pragma unroll
        for (int dg = 0; dg < 8; dg++) {
            O[dg][0] *= sc0; O[dg][1] *= sc0; O[dg][2] *= sc1; O[dg][3] *= sc1;
        }
        #pragma unroll
        for (int g = 0; g < 16; g++) {
            const float p0 = __expf(c_[g][0] - mr0), p1 = __expf(c_[g][1] - mr0);
            const float p2 = __expf(c_[g][2] - mr1), p3 = __expf(c_[g][3] - mr1);
            c_[g][0] = p0; c_[g][1] = p1; c_[g][2] = p2; c_[g][3] = p3;
            l0 += p0 + p1; l1 += p2 + p3;
        }

        #pragma unroll
        for (int kc2 = 0; kc2 < 8; kc2++) {
            uint32_t a[4];
            a[0] = pack2(c_[2 * kc2][0],     c_[2 * kc2][1]);
            a[1] = pack2(c_[2 * kc2][2],     c_[2 * kc2][3]);
            a[2] = pack2(c_[2 * kc2 + 1][0], c_[2 * kc2 + 1][1]);
            a[3] = pack2(c_[2 * kc2 + 1][2], c_[2 * kc2 + 1][3]);
            #pragma unroll
            for (int dgp = 0; dgp < 4; dgp++) {
                uint32_t bb[4];
                ldm_x4_t(bb, vu + (uint32_t)((kc2 * 16 + (lane & 15)) * 144
                                             + (dgp * 16 + ((lane >> 4) << 3)) * 2));
                mma16816<false>(O[2 * dgp],     a, bb);
                mma16816<false>(O[2 * dgp + 1], a, bb + 2);
            }
        }
        __syncthreads();
        if (c + 2 < NSTEP) issueKV(c + 2, c & 1);
    }

    l0 += __shfl_xor_sync(~0u, l0, 1); l0 += __shfl_xor_sync(~0u, l0, 2);
    l1 += __shfl_xor_sync(~0u, l1, 1); l1 += __shfl_xor_sync(~0u, l1, 2);
    const float i0 = 1.f / l0, i1 = 1.f / l1;
    const size_t row0 = (size_t)(b * Nq + n0 + nw + r) * Dq + hh * DHq;
    const size_t row1 = row0 + 8 * Dq;
    #pragma unroll
    for (int dg = 0; dg < 8; dg++) {
        const int d = dg * 8 + ((lane & 3) << 1);
        *(__nv_bfloat162*)(Mhi + row0 + d) =
            __float22bfloat162_rn(make_float2(O[dg][0] * i0, O[dg][1] * i0));
        *(__nv_bfloat162*)(Mhi + row1 + d) =
            __float22bfloat162_rn(make_float2(O[dg][2] * i1, O[dg][3] * i1));
    }
}

// ---------------- fused weight transpose + h split (one launch) --------------
__device__ __forceinline__ void wtile_b(const float* __restrict__ W, __nv_bfloat16* __restrict__ T,
                                        int K, int Nc, int k0, int n0, int tx, int ty,
                                        float t[32][33]) {
    #pragma unroll
    for (int i = ty; i < 32; i += 8) t[i][tx] = W[(size_t)(k0 + i) * Nc + n0 + tx];
    __syncthreads();
    #pragma unroll
    for (int i = ty; i < 32; i += 8)
        T[(size_t)(n0 + i) * K + k0 + tx] = __float2bfloat16(t[tx][i]);
}
__device__ __forceinline__ void wtile_h(const float* __restrict__ W, __half* __restrict__ T,
                                        int K, int Nc, int k0, int n0, int tx, int ty,
                                        float t[32][33]) {
    #pragma unroll
    for (int i = ty; i < 32; i += 8) t[i][tx] = W[(size_t)(k0 + i) * Nc + n0 + tx];
    __syncthreads();
    #pragma unroll
    for (int i = ty; i < 32; i += 8)
        T[(size_t)(n0 + i) * K + k0 + tx] = __float2half_rn(t[tx][i]);
}

__global__ void wtrans_all_kernel(
    const float* Wq, const float* Wk, const float* Wv, const float* Wo,
    const float* W1, const float* W2, const float* h,
    __nv_bfloat16* qkvT, __nv_bfloat16* oT, __half* w1T, __half* w2T,
    __nv_bfloat16* hhi)
{
    __shared__ float t[32][33];
    const int tx = threadIdx.x, ty = threadIdx.y;
    const int tid = ty * 32 + tx;
    int id = blockIdx.x;
    if (id < 1024) {
        const int w = id >> 8, tl = id & 255;
        const int n0 = (tl & 15) * 32, k0 = (tl >> 4) * 32;
        const float* W = (w == 0) ? Wq : (w == 1) ? Wk : (w == 2) ? Wv : Wo;
        __nv_bfloat16* T = (w < 3) ? (qkvT + (size_t)w * Dq * Dq) : oT;
        wtile_b(W, T, Dq, Dq, k0, n0, tx, ty, t);
    } else if (id < 2048) {
        const int tl = id - 1024;
        wtile_h(W1, w1T, Dq, Fq, (tl >> 6) * 32, (tl & 63) * 32, tx, ty, t);
    } else if (id < 3072) {
        const int tl = id - 2048;
        wtile_h(W2, w2T, Fq, Dq, (tl >> 4) * 32, (tl & 15) * 32, tx, ty, t);
    } else {
        const size_t base = (size_t)(id - 3072) * 4096 + tid * 16;
        #pragma unroll
        for (int i = 0; i < 4; i++) {
            const float4 v = *(const float4*)(h + base + i * 4);
            __nv_bfloat162 p0 = __float22bfloat162_rn(make_float2(v.x, v.y));
            __nv_bfloat162 p1 = __float22bfloat162_rn(make_float2(v.z, v.w));
            *(__nv_bfloat162*)(hhi + base + i * 4)     = p0;
            *(__nv_bfloat162*)(hhi + base + i * 4 + 2) = p1;
        }
    }
}

// ---------------- 8-wide projection + cos/sin / phase update -----------------
// grid ROWS/32, 256 threads; warp handles 4 rows
__global__ __launch_bounds__(256) void proj8_kernel(
    const float* __restrict__ X, const float* __restrict__ W8,
    const float* __restrict__ b8, const float* __restrict__ phases,
    float* __restrict__ out, float* __restrict__ cph, float* __restrict__ sph, int mode)
{
    __shared__ float w8t[8][516];
    __shared__ float b8s[8];
    const int tid = threadIdx.x;
    for (int i = tid; i < Dq * Hq; i += 256) w8t[i & 7][i >> 3] = W8[i];
    if (tid < 8) b8s[tid] = b8[tid];
    __syncthreads();
    const int warp = tid >> 5, lane = tid & 31;
    #pragma unroll
    for (int rr = 0; rr < 4; rr++) {
        const int row = blockIdx.x * 32 + warp * 4 + rr;
        const float4* X4 = (const float4*)(X + (size_t)row * Dq);
        float acc[8] = {0.f, 0.f, 0.f, 0.f, 0.f, 0.f, 0.f, 0.f};
        #pragma unroll
        for (int i = 0; i < 4; i++) {
            const int c4 = lane + i * 32;
            const float4 xv = X4[c4];
            #pragma unroll
            for (int w = 0; w < 8; w++) {
                const float4 wv = ((const float4*)&w8t[w][0])[c4];
                acc[w] += xv.x * wv.x + xv.y * wv.y + xv.z * wv.z + xv.w * wv.w;
            }
        }
        #pragma unroll
        for (int w = 0; w < 8; w++)
            #pragma unroll
            for (int o = 16; o; o >>= 1) acc[w] += __shfl_xor_sync(~0u, acc[w], o);
        if (lane < 8) {
            float s = b8s[lane];
            #pragma unroll
            for (int w = 0; w < 8; w++) if (lane == w) s += acc[w];
            if (mode) {
                out[(size_t)row * Hq + lane] = phases[(size_t)row * Hq + lane]
                                               + 0.31415926535897932f * tanhf(s);
            } else {
                out[(size_t)row * Hq + lane] = s;
                const int b = row >> 11, n = row & 2047;
                cph[(size_t)(b * Hq + lane) * Nq + n] = cosf(s);
                sph[(size_t)(b * Hq + lane) * Nq + n] = sinf(s);
            }
        }
    }
}

// ---------------- residual add + LayerNorm (warp per row) --------------------
// oh16: optional fp16 copy of output ; href/rn: optional ||out - href|| per row
__global__ __launch_bounds__(256) void addln_kernel(
    const float* __restrict__ X, const float* __restrict__ Y,
    const float* __restrict__ g, const float* __restrict__ be,
    float* __restrict__ out, __half* __restrict__ oh16,
    const float* __restrict__ href, float* __restrict__ rn)
{
    const int warp = threadIdx.x >> 5, lane = threadIdx.x & 31;
    const size_t row = blockIdx.x * 8 + warp;
    const float4* X4 = (const float4*)(X + row * Dq);
    const float4* Y4 = (const float4*)(Y + row * Dq);
    float a[16];
    float s = 0.f;
    #pragma unroll
    for (int i = 0; i < 4; i++) {
        const float4 xv = X4[lane + i * 32];
        const float4 yv = Y4[lane + i * 32];
        a[4 * i + 0] = xv.x + yv.x; a[4 * i + 1] = xv.y + yv.y;
        a[4 * i + 2] = xv.z + yv.z; a[4 * i + 3] = xv.w + yv.w;
        s += a[4 * i] + a[4 * i + 1] + a[4 * i + 2] + a[4 * i + 3];
    }
    #pragma unroll
    for (int o = 16; o; o >>= 1) s += __shfl_xor_sync(~0u, s, o);
    const float mu = s * (1.f / Dq);
    float vs = 0.f;
    #pragma unroll
    for (int i = 0; i < 16; i++) { const float d = a[i] - mu; vs += d * d; }
    #pragma unroll
    for (int o = 16; o; o >>= 1) vs += __shfl_xor_sync(~0u, vs, o);
    const float rstd = rsqrtf(vs * (1.f / Dq) + 1e-5f);
    float ss = 0.f;
    #pragma unroll
    for (int i = 0; i < 4; i++) {
        const int c4 = lane + i * 32;
        const float4 gv = ((const float4*)g)[c4];
        const float4 bv = ((const float4*)be)[c4];
        float4 r;
        r.x = (a[4 * i + 0] - mu) * rstd * gv.x + bv.x;
        r.y = (a[4 * i + 1] - mu) * rstd * gv.y + bv.y;
        r.z = (a[4 * i + 2] - mu) * rstd * gv.z + bv.z;
        r.w = (a[4 * i + 3] - mu) * rstd * gv.w + bv.w;
        ((float4*)(out + row * Dq))[c4] = r;
        if (oh16) {
            __half2 p0 = __floats2half2_rn(r.x, r.y);
            __half2 p1 = __floats2half2_rn(r.z, r.w);
            *(__half2*)(oh16 + row * Dq + c4 * 4)     = p0;
            *(__half2*)(oh16 + row * Dq + c4 * 4 + 2) = p1;
        }
        if (href) {
            const float4 hv = ((const float4*)(href + row * Dq))[c4];
            const float d0 = r.x - hv.x, d1 = r.y - hv.y, d2 = r.z - hv.z, d3 = r.w - hv.w;
            ss += d0 * d0 + d1 * d1 + d2 * d2 + d3 * d3;
        }
    }
    if (href) {
        #pragma unroll
        for (int o = 16; o; o >>= 1) ss += __shfl_xor_sync(~0u, ss, o);
        if (lane == 0) rn[row] = sqrtf(ss);
    }
}

__global__ void delta_kernel(const float* __restrict__ rn, float* __restrict__ out) {
    __shared__ float red[256];
    const int tid = threadIdx.x;
    float s = 0.f;
    for (int i = tid; i < ROWS; i += 256) s += rn[i];
    red[tid] = s; __syncthreads();
    #pragma unroll
    for (int o = 128; o; o >>= 1) { if (tid < o) red[tid] += red[tid + o]; __syncthreads(); }
    if (tid == 0) out[0] = red[0] * (1.f / ROWS);
}

// ---------------- launch ------------------------------------------------------
extern "C" void kernel_launch(void* const* d_in, const int* in_sizes, int n_in,
                              void* d_out, int out_size) {
    const float* h      = (const float*)d_in[0];
    const float* phases = (const float*)d_in[1];
    const unsigned char* mask = (const unsigned char*)d_in[2];
    const float* Wq  = (const float*)d_in[3];
    const float* Wk  = (const float*)d_in[4];
    const float* Wp  = (const float*)d_in[5];
    const float* bp  = (const float*)d_in[6];
    const float* Wv  = (const float*)d_in[7];
    const float* Wo  = (const float*)d_in[8];
    const float* W1  = (const float*)d_in[9];
    const float* b1  = (const float*)d_in[10];
    const float* W2  = (const float*)d_in[11];
    const float* b2  = (const float*)d_in[12];
    const float* g1  = (const float*)d_in[13];
    const float* be1 = (const float*)d_in[14];
    const float* g2  = (const float*)d_in[15];
    const float* be2 = (const float*)d_in[16];
    const float* Wph = (const float*)d_in[17];
    const float* bph = (const float*)d_in[18];

    float* out_h2     = (float*)d_out;
    float* out_phases = out_h2 + (size_t)ROWS * Dq;
    float* out_delta  = out_phases + (size_t)ROWS * Hq;

    float *ph, *cphp, *sphp, *msgO, *h1, *ffn2, *rn;
    __nv_bfloat16 *QKVb, *hhi, *mhi, *WqkvT, *WoT;
    __half *h1h, *f1h, *W1T, *W2T;
    cudaGetSymbolAddress((void**)&ph, g_ph);
    cudaGetSymbolAddress((void**)&cphp, g_cph); cudaGetSymbolAddress((void**)&sphp, g_sph);
    cudaGetSymbolAddress((void**)&msgO, g_msgO);
    cudaGetSymbolAddress((void**)&h1, g_h1);    cudaGetSymbolAddress((void**)&ffn2, g_ffn2);
    cudaGetSymbolAddress((void**)&rn, g_rn);
    cudaGetSymbolAddress((void**)&QKVb, g_QKVb);
    cudaGetSymbolAddress((void**)&hhi, g_h_hi);
    cudaGetSymbolAddress((void**)&mhi, g_msg_hi);
    cudaGetSymbolAddress((void**)&h1h, g_h1h);
    cudaGetSymbolAddress((void**)&f1h, g_ffn1h);
    cudaGetSymbolAddress((void**)&WqkvT, g_WqkvT);
    cudaGetSymbolAddress((void**)&WoT, g_WoT);
    cudaGetSymbolAddress((void**)&W1T, g_W1T);
    cudaGetSymbolAddress((void**)&W2T, g_W2T);

    const int smG = 4 * 2 * TILE_B;           // 81920
    cudaFuncSetAttribute(flash_kernel, cudaFuncAttributeMaxDynamicSharedMemorySize, FLASH_SMEM);
    cudaFuncSetAttribute((const void*)tgemm_kernel<4, false>, cudaFuncAttributeMaxDynamicSharedMemorySize, smG);
    cudaFuncSetAttribute((const void*)tgemm_kernel<4, true>,  cudaFuncAttributeMaxDynamicSharedMemorySize, smG);

    // weights transpose + h->bf16, one launch
    wtrans_all_kernel<<<3584, dim3(32, 8)>>>(Wq, Wk, Wv, Wo, W1, W2, h,
                                             WqkvT, WoT, W1T, W2T, hhi);

    // fused QKV projection -> bf16
    tgemm_kernel<4, false><<<dim3(QKVS / 128, ROWS / 128), 256, smG>>>(
        (const uint16_t*)hhi, (const uint16_t*)WqkvT, nullptr,
        nullptr, (uint16_t*)QKVb, Dq, QKVS, 8);
    proj8_kernel<<<ROWS / 32, 256>>>(h, Wp, bp, nullptr, ph, cphp, sphp, 0);

    // fused flash attention
    flash_kernel<<<dim3(Nq / 128, BHq), 256, FLASH_SMEM>>>(QKVb, cphp, sphp, mask, mhi);

    // Wo projection (bf16 -> fp32)
    tgemm_kernel<4, false><<<dim3(Dq / 128, ROWS / 128), 256, smG>>>(
        (const uint16_t*)mhi, (const uint16_t*)WoT, nullptr,
        msgO, nullptr, Dq, Dq, 0);
    addln_kernel<<<ROWS / 8, 256>>>(h, msgO, g1, be1, h1, h1h, nullptr, nullptr);

    // FFN (single-term fp16)
    tgemm_kernel<4, true><<<dim3(Fq / 128, ROWS / 128), 256, smG>>>(
        (const uint16_t*)h1h, (const uint16_t*)W1T, b1,
        nullptr, (uint16_t*)f1h, Dq, Fq, 11);            // bias + gelu + fp16 out
    tgemm_kernel<4, true><<<dim3(Dq / 128, ROWS / 128), 256, smG>>>(
        (const uint16_t*)f1h, (const uint16_t*)W2T, b2,
        ffn2, nullptr, Fq, Dq, 1);                        // bias, fp32 out
    addln_kernel<<<ROWS / 8, 256>>>(h1, ffn2, g2, be2, out_h2, nullptr, h, rn);

    // phase update + delta
    proj8_kernel<<<ROWS / 32, 256>>>(out_h2, Wph, bph, phases, out_phases, nullptr, nullptr, 1);
    delta_kernel<<<1, 256>>>(rn, out_delta);
}